// round 11
// baseline (speedup 1.0000x reference)
#include <cuda_runtime.h>
#include <cuda_fp16.h>
#include <math.h>

#define Nn   20000
#define Ee   320000
#define Gg   16
#define TAB  8192
#define RMAXf 4.0f
#define RINf  3.5f
#define PI_F  3.14159265358979f
#define SQRT3f 1.7320508075688772f
#define INV_SQRT3f 0.5773502691896258f

#define NBs 157   // (Nn+127)/128
#define NBv 469   // (3*Nn+127)/128

// ---------------- device scratch ----------------
__device__ __align__(16) float g_s  [Nn*64];
__device__ __align__(16) float g_v  [Nn*96];     // raw o_v, rows (n*3+c) x 32
__device__ __align__(16) float g_s1 [Nn*64];
__device__ __align__(16) float g_v1 [Nn*96];
__device__ __align__(16) float g_scs[Nn*96];
__device__ __align__(16) float g_as [Nn*96];
__device__ __align__(16) float g_av [Nn*288];
__device__ __align__(16) float g_gate[Nn*32];
__device__ __align__(16) float g_tab [2*(TAB+1)*192];
__device__ __align__(16) __half2 g_tabh[2*TAB*192];
__device__ __align__(16) float4 g_edir[Ee];      // {x, shx, shy, shz}
__device__ int   g_esrc[Ee];
__device__ float g_atomic[Nn];
__device__ int   g_cnt[Nn];
__device__ int   g_off[Nn+1];
__device__ int   g_cur[Nn];
__device__ int   g_elist[Ee];

struct __align__(8) H2x2 { __half2 a, b; };

__device__ __forceinline__ float silu_f(float x){ return x / (1.0f + expf(-x)); }

__device__ __forceinline__ unsigned long long packdup(float a){
    unsigned long long r;
    asm("mov.b64 %0, {%1, %1};" : "=l"(r) : "f"(a));
    return r;
}
__device__ __forceinline__ void unpack2(unsigned long long v, float& lo, float& hi){
    asm("mov.b64 {%0, %1}, %2;" : "=f"(lo), "=f"(hi) : "l"(v));
}
__device__ __forceinline__ void fma2(unsigned long long& d, unsigned long long a, unsigned long long b){
    asm("fma.rn.f32x2 %0, %1, %2, %0;" : "+l"(d) : "l"(a), "l"(b));
}

// ---------------- CSR ----------------
__global__ void k_zero_init(){
    int i = blockIdx.x*256 + threadIdx.x;
    if (i < Nn) g_cnt[i] = 0;
}

__global__ void k_count(const int* __restrict__ recv){
    int e = blockIdx.x*256 + threadIdx.x;
    if (e < Ee) atomicAdd(&g_cnt[recv[e]], 1);
}

__global__ void k_scan(){
    const int PER = 20;
    int t = threadIdx.x;
    int base = t * PER;
    int loc[PER]; int s = 0;
    #pragma unroll
    for (int i = 0; i < PER; i++){
        int idx = base + i;
        int x = (idx < Nn) ? g_cnt[idx] : 0;
        loc[i] = s; s += x;
    }
    int lane = t & 31, wid = t >> 5;
    int v = s;
    #pragma unroll
    for (int o = 1; o < 32; o <<= 1){
        int y = __shfl_up_sync(0xffffffffu, v, o);
        if (lane >= o) v += y;
    }
    __shared__ int wsum[32];
    if (lane == 31) wsum[wid] = v;
    __syncthreads();
    if (wid == 0){
        int w = wsum[lane];
        #pragma unroll
        for (int o = 1; o < 32; o <<= 1){
            int y = __shfl_up_sync(0xffffffffu, w, o);
            if (lane >= o) w += y;
        }
        wsum[lane] = w;
    }
    __syncthreads();
    int excl = v - s + (wid ? wsum[wid-1] : 0);
    #pragma unroll
    for (int i = 0; i < PER; i++){
        int idx = base + i;
        int off = excl + loc[i];
        if (idx < Nn){ g_off[idx] = off; g_cur[idx] = off; }
        else if (idx == Nn) g_off[Nn] = off;
    }
}

__global__ void k_scatter(const int* __restrict__ recv){
    int e = blockIdx.x*256 + threadIdx.x;
    if (e < Ee){
        int p = atomicAdd(&g_cur[recv[e]], 1);
        g_elist[p] = e;
    }
}

// ---------------- sort (smem-staged) + cooperative edge records ----------------
#define SORT_NB  79          // (Nn+255)/256
#define SCAP     5120

__global__ void k_sortrec(const float* __restrict__ dR, const int* __restrict__ senders){
    __shared__ int se[SCAP];
    int blk = blockIdx.x, tid = threadIdx.x;
    int n = blk*256 + tid;
    int n0 = blk*256;
    int n1 = n0 + 256; if (n1 > Nn) n1 = Nn;
    int p0 = g_off[n0], p1 = g_off[n1];
    int cnt = p1 - p0;
    if (cnt <= SCAP){
        for (int i = tid; i < cnt; i += 256) se[i] = g_elist[p0 + i];
        __syncthreads();
        if (n < Nn){
            int b = g_off[n] - p0, e2 = g_off[n+1] - p0;
            for (int i = b+1; i < e2; i++){
                int key = se[i];
                int j = i-1;
                while (j >= b && se[j] > key){ se[j+1] = se[j]; j--; }
                se[j+1] = key;
            }
        }
        __syncthreads();
        for (int p = p0 + tid; p < p1; p += 256){
            int e = se[p - p0];
            float dx = dR[3*e+0], dy = dR[3*e+1], dz = dR[3*e+2];
            float r = sqrtf(dx*dx + dy*dy + dz*dz);
            float inv = 1.0f / fmaxf(r, 1e-6f);
            float x = fminf(r * ((float)TAB / RMAXf), (float)TAB);
            g_edir[p] = make_float4(x, SQRT3f*dx*inv, SQRT3f*dy*inv, SQRT3f*dz*inv);
            g_esrc[p] = senders[e];
        }
    } else {
        // statistical fallback: global-memory sort
        if (n < Nn){
            int b = g_off[n], e2 = g_off[n+1];
            for (int i = b+1; i < e2; i++){
                int key = g_elist[i];
                int j = i-1;
                while (j >= b && g_elist[j] > key){ g_elist[j+1] = g_elist[j]; j--; }
                g_elist[j+1] = key;
            }
        }
        __syncthreads();
        for (int p = p0 + tid; p < p1; p += 256){
            int e = g_elist[p];
            float dx = dR[3*e+0], dy = dR[3*e+1], dz = dR[3*e+2];
            float r = sqrtf(dx*dx + dy*dy + dz*dz);
            float inv = 1.0f / fmaxf(r, 1e-6f);
            float x = fminf(r * ((float)TAB / RMAXf), (float)TAB);
            g_edir[p] = make_float4(x, SQRT3f*dx*inv, SQRT3f*dy*inv, SQRT3f*dz*inv);
            g_esrc[p] = senders[e];
        }
    }
}

// ---------------- embedding ----------------
__global__ void k_embed(const float* __restrict__ nodes, const float* __restrict__ Wemb){
    int idx = blockIdx.x*256 + threadIdx.x;
    if (idx >= Nn*64) return;
    int n = idx >> 6, o = idx & 63;
    float acc = 0.f;
    #pragma unroll
    for (int e = 0; e < 4; e++) acc = fmaf(nodes[n*4+e], Wemb[e*64+o], acc);
    g_s[idx] = acc * 0.5f;
}

// ---------------- radial table ----------------
#define TROWS    (2*(TAB+1))
#define TAB_NB   ((TROWS+3)/4)

__global__ void k_table(const float* __restrict__ Wr0, const float* __restrict__ Wr1,
                        const float* __restrict__ Wr2){
    __shared__ float h1s[4][64];
    __shared__ float h2s[4][64];
    int tid = threadIdx.x;
    int q = blockIdx.x*4 + (tid >> 6);
    int t = tid & 63, sub = tid >> 6;
    bool act = (q < TROWS);
    int l = act ? q / (TAB+1) : 0;
    int row = act ? q % (TAB+1) : 0;
    const float* R0 = Wr0 + l*512;
    const float* R1 = Wr1 + l*4096;
    const float* R2 = Wr2 + l*12288;
    float r = (float)row * (RMAXf / (float)TAB);
    float rs = fmaxf(r, 1e-6f);
    float env;
    if (r < RINf) env = 1.0f;
    else if (r > RMAXf) env = 0.0f;
    else { float tt = (r - RINf) / (RMAXf - RINf); env = 0.5f*(cosf(PI_F*tt)+1.0f); }
    float remb[8];
    #pragma unroll
    for (int nb = 1; nb <= 8; nb++)
        remb[nb-1] = 0.70710678f * sinf((float)nb * PI_F * rs / RMAXf) / rs * env;
    float h = 0.f;
    #pragma unroll
    for (int k = 0; k < 8; k++) h = fmaf(remb[k], R0[k*64+t], h);
    h1s[sub][t] = silu_f(h * 0.35355339f);
    __syncthreads();
    float h2 = 0.f;
    #pragma unroll
    for (int k = 0; k < 64; k++) h2 = fmaf(h1s[sub][k], R1[k*64+t], h2);
    h2s[sub][t] = silu_f(h2 * 0.125f);
    __syncthreads();
    if (act){
        #pragma unroll
        for (int j = 0; j < 3; j++){
            int o = t + 64*j;
            float w = 0.f;
            #pragma unroll 8
            for (int k = 0; k < 64; k++) w = fmaf(h2s[sub][k], R2[k*192+o], w);
            g_tab[q*192 + o] = w * 0.125f;
        }
    }
}

__global__ void k_pack(){
    int idx = blockIdx.x*256 + threadIdx.x;
    if (idx >= 2*TAB*192) return;
    int l   = idx / (TAB*192);
    int rem = idx % (TAB*192);
    int row = rem / 192, o = rem % 192;
    float v0 = g_tab[(l*(TAB+1) + row    )*192 + o];
    float v1 = g_tab[(l*(TAB+1) + row + 1)*192 + o];
    g_tabh[idx] = __floats2half2_rn(v0, v1 - v0);
}

// ---------------- gemm body (f32x2 packed, 8 contiguous rows/thread) ----------------
#define AS_STRIDE 132
template<int K, int NC, int MODE, int ASTRIDE>
__device__ __forceinline__ void gemm_body(float* sm,
            const float* __restrict__ A, const float* __restrict__ B,
            const float* __restrict__ D, float* __restrict__ C,
            const float* __restrict__ attrs, int M, float alpha, int blk){
    constexpr int TN = NC / 16;
    constexpr int TH = TN / 2;
    float* As = sm;                    // [16][AS_STRIDE]
    float* Bs = sm + 16*AS_STRIDE;     // [16][NC]
    int tid = threadIdx.x;
    int mg = tid & 15, ng = tid >> 4;
    int m0 = blk * 128;
    unsigned long long acc2[8][TH];
    #pragma unroll
    for (int i = 0; i < 8; i++)
        #pragma unroll
        for (int j = 0; j < TH; j++) acc2[i][j] = 0ull;

    for (int kc = 0; kc < K; kc += 16){
        #pragma unroll
        for (int q = 0; q < 8; q++){
            int e2 = q*256 + tid;
            int r = e2 >> 4, c = e2 & 15;
            int row = m0 + r;
            float val = 0.f;
            if (row < M){
                int k = kc + c;
                if (MODE == 1)      val = A[row*64 + (k>>2)] * attrs[row*4 + (k&3)];
                else if (MODE == 5) val = A[row*32 + k] * attrs[(row/3)*32 + k];
                else                val = A[row*ASTRIDE + k];
            }
            As[c*AS_STRIDE + r] = val;
        }
        for (int e2 = tid; e2 < 16*NC; e2 += 256){
            int r = e2 / NC, c = e2 % NC;
            Bs[r*NC + c] = B[(kc+r)*NC + c];
        }
        __syncthreads();
        #pragma unroll
        for (int kk = 0; kk < 16; kk++){
            const float4* ap = (const float4*)(As + kk*AS_STRIDE + mg*8);
            float4 a0 = ap[0], a1 = ap[1];
            float aa[8] = {a0.x, a0.y, a0.z, a0.w, a1.x, a1.y, a1.z, a1.w};
            unsigned long long aa2[8];
            #pragma unroll
            for (int i = 0; i < 8; i++) aa2[i] = packdup(aa[i]);
            const unsigned long long* bp =
                (const unsigned long long*)(Bs + kk*NC + ng*TN);
            unsigned long long bb2[TH];
            #pragma unroll
            for (int j = 0; j < TH; j++) bb2[j] = bp[j];
            #pragma unroll
            for (int i = 0; i < 8; i++)
                #pragma unroll
                for (int j = 0; j < TH; j++) fma2(acc2[i][j], aa2[i], bb2[j]);
        }
        __syncthreads();
    }
    #pragma unroll
    for (int i = 0; i < 8; i++){
        int row = m0 + mg*8 + i;
        if (row >= M) continue;
        #pragma unroll
        for (int j = 0; j < TH; j++){
            float vlo, vhi;
            unpack2(acc2[i][j], vlo, vhi);
            int col = ng*TN + 2*j;
            float val0 = vlo * alpha;
            float val1 = vhi * alpha;
            if (MODE == 2){
                val0 += D[row*96 + col];
                val1 += D[row*96 + col + 1];
                float sv0 = silu_f(val0);
                float sv1 = silu_f(val1);
                if (col < 64){
                    g_s[row*64 + col]   = sv0;
                    g_s[row*64 + col+1] = sv1;
                } else {
                    g_gate[row*32 + (col-64)]   = sv0;
                    g_gate[row*32 + (col-64)+1] = sv1;
                }
            } else {
                C[row*NC + col]   = val0;
                C[row*NC + col+1] = val1;
            }
        }
    }
}

#define A_SCS 0.0625f
#define A_S1  0.125f
#define A_V1  0.17677669529f
#define A_O   0.10206207262f

#define SM_FLOATS (16*AS_STRIDE + 16*96)

// sc_s alone (side stream; overlaps gather)
__global__ __launch_bounds__(256, 2)
void k_scs(const float* __restrict__ nodes, const float* __restrict__ WscS){
    __shared__ __align__(16) float sm[SM_FLOATS];
    gemm_body<256,96,1,256>(sm, g_s, WscS, nullptr, g_scs, nodes, Nn, A_SCS, blockIdx.x);
}

// l1_s layer 0 alone
__global__ __launch_bounds__(256, 2)
void k_l1s0(const float* __restrict__ Wl1s){
    __shared__ __align__(16) float sm[SM_FLOATS];
    gemm_body<64,64,0,64>(sm, g_s, Wl1s, nullptr, g_s1, nullptr, Nn, A_S1, blockIdx.x);
}

// layer 1: l1_s | gated l1_v
__global__ __launch_bounds__(256, 2)
void k_l1grp1(const float* __restrict__ Wl1s, const float* __restrict__ Wl1v){
    __shared__ __align__(16) float sm[SM_FLOATS];
    int b = blockIdx.x;
    if (b < NBs) gemm_body<64,64,0,64>(sm, g_s, Wl1s, nullptr, g_s1, nullptr, Nn, A_S1, b);
    else         gemm_body<32,32,5,32>(sm, g_v, Wl1v, nullptr, g_v1, g_gate, 3*Nn, A_V1, b-NBs);
}

// phase B, layer 0: l2_s (K=64 effective) | l2_v (K=64 effective)
__global__ __launch_bounds__(256, 2)
void k_phB0(const float* __restrict__ Wl2s, const float* __restrict__ Wl2v){
    __shared__ __align__(16) float sm[SM_FLOATS];
    int b = blockIdx.x;
    if (b < NBs) gemm_body<64,96,2,96>(sm, g_as, Wl2s, g_scs, nullptr, nullptr, Nn, A_O, b);
    else         gemm_body<64,32,0,96>(sm, g_av, Wl2v, nullptr, g_v, nullptr, 3*Nn, A_O, b-NBs);
}

// phase B, layer 1: l2_s only (full K=96)
__global__ __launch_bounds__(256, 2)
void k_phB1(const float* __restrict__ Wl2s){
    __shared__ __align__(16) float sm[SM_FLOATS];
    gemm_body<96,96,2,96>(sm, g_as, Wl2s, g_scs, nullptr, nullptr, Nn, A_O, blockIdx.x);
}

// ---------------- gather (lane l owns features 2l, 2l+1) ----------------
template<int LAYER>
__global__ void k_gather(){
    int n = blockIdx.x*8 + threadIdx.y;
    if (n >= Nn) return;
    int l = threadIdx.x;
    const __half2* tb_base = g_tabh + LAYER*(TAB*192);
    int beg = g_off[n], end = g_off[n+1];
    float as0 = 0.f, as1 = 0.f, as2 = 0.f;
    float av00=0,av01=0, av10=0,av11=0, av20=0,av21=0;
    for (int p = beg; p < end; p++){
        float4 d = g_edir[p];
        int src = g_esrc[p];
        int gi = (int)d.x; gi = min(gi, TAB-1);
        float f = d.x - (float)gi;
        const __half2* t0 = tb_base + gi*192;
        H2x2 w1 = *reinterpret_cast<const H2x2*>(t0 + 2*l);
        float w1a = __low2float(w1.a) + f*__high2float(w1.a);
        float w1b = __low2float(w1.b) + f*__high2float(w1.b);
        float2 se = *reinterpret_cast<const float2*>(&g_s1[src*64 + 2*l]);
        as0 = fmaf(w1a, se.x, as0);
        as1 = fmaf(w1b, se.y, as1);
        if (LAYER == 0){
            H2x2 w2 = *reinterpret_cast<const H2x2*>(t0 + 64 + 2*l);
            float w2a = __low2float(w2.a) + f*__high2float(w2.a);
            float w2b = __low2float(w2.b) + f*__high2float(w2.b);
            float p2a = w2a*se.x, p2b = w2b*se.y;
            av00 = fmaf(p2a, d.y, av00); av10 = fmaf(p2a, d.z, av10); av20 = fmaf(p2a, d.w, av20);
            av01 = fmaf(p2b, d.y, av01); av11 = fmaf(p2b, d.z, av11); av21 = fmaf(p2b, d.w, av21);
        } else {
            __half2 h4 = t0[160 + l];
            float w4 = __low2float(h4) + f*__high2float(h4);
            float ve0 = g_v1[src*96 +      l];
            float ve1 = g_v1[src*96 + 32 + l];
            float ve2 = g_v1[src*96 + 64 + l];
            float dv = ve0*d.y + ve1*d.z + ve2*d.w;
            as2 = fmaf(w4*INV_SQRT3f, dv, as2);
        }
    }
    const float sc = 0.25f;
    *reinterpret_cast<float2*>(&g_as[n*96 + 2*l]) = make_float2(as0*sc, as1*sc);
    if (LAYER == 0){
        int b0 = n*288;
        *reinterpret_cast<float2*>(&g_av[b0 +       2*l]) = make_float2(av00*sc, av01*sc);
        *reinterpret_cast<float2*>(&g_av[b0 +  96 + 2*l]) = make_float2(av10*sc, av11*sc);
        *reinterpret_cast<float2*>(&g_av[b0 + 192 + 2*l]) = make_float2(av20*sc, av21*sc);
    } else {
        g_as[n*96 + 64 + l] = as2*sc;
    }
}

// ---------------- heads ----------------
__global__ void k_head(const float* __restrict__ nodes,
                       const float* __restrict__ Wen1, const float* __restrict__ Wen2,
                       const float* __restrict__ Wmag1, const float* __restrict__ Wmag2,
                       const float* __restrict__ sc_occ, const float* __restrict__ sh_occ,
                       const float* __restrict__ esc, const float* __restrict__ esh,
                       float* __restrict__ out){
    int n = blockIdx.x*8 + threadIdx.y;
    if (n >= Nn) return;
    int t = threadIdx.x;
    const float* s = g_s + n*64;
    float he = 0.f, hm = 0.f;
    #pragma unroll 8
    for (int i = 0; i < 64; i++){
        float si = s[i];
        he = fmaf(si, Wen1[i*32+t], he);
        hm = fmaf(si, Wmag1[i*32+t], hm);
    }
    he *= 0.125f; hm *= 0.125f;
    float pe  = he * Wen2[t];
    float pm0 = hm * Wmag2[t*2+0];
    float pm1 = hm * Wmag2[t*2+1];
    #pragma unroll
    for (int o = 16; o; o >>= 1){
        pe  += __shfl_down_sync(0xffffffffu, pe,  o);
        pm0 += __shfl_down_sync(0xffffffffu, pm0, o);
        pm1 += __shfl_down_sync(0xffffffffu, pm1, o);
    }
    if (t == 0){
        g_atomic[n] = esc[0] * (pe * 0.17677669529f) + esh[0];
        float a0 = nodes[n*4+0], a1 = nodes[n*4+1], a2 = nodes[n*4+2];
        float s0 = a0*sc_occ[0] + a1*sc_occ[2] + a2*sc_occ[4];
        float s1m= a0*sc_occ[1] + a1*sc_occ[3] + a2*sc_occ[5];
        float t0 = a0*sh_occ[0] + a1*sh_occ[2] + a2*sh_occ[4];
        float t1 = a0*sh_occ[1] + a1*sh_occ[3] + a2*sh_occ[5];
        out[Gg + n*2 + 0] = s0 *(pm0 * 0.17677669529f) + t0;
        out[Gg + n*2 + 1] = s1m*(pm1 * 0.17677669529f) + t1;
    }
}

__global__ void k_energy(const int* __restrict__ n_node, float* __restrict__ out){
    __shared__ float sm[256];
    int g = blockIdx.x, t = threadIdx.x;
    int start = 0;
    for (int q = 0; q < g; q++) start += n_node[q];
    int end = start + n_node[g];
    if (start > Nn) start = Nn;
    if (end > Nn) end = Nn;
    float acc = 0.f;
    for (int i = start + t; i < end; i += 256) acc += g_atomic[i];
    sm[t] = acc; __syncthreads();
    #pragma unroll
    for (int o = 128; o; o >>= 1){ if (t < o) sm[t] += sm[t+o]; __syncthreads(); }
    if (t == 0) out[g] = sm[0];
}

// ---------------- launch ----------------
extern "C" void kernel_launch(void* const* d_in, const int* in_sizes, int n_in,
                              void* d_out, int out_size){
    const float* nodes   = (const float*)d_in[0];
    const float* dR      = (const float*)d_in[1];
    const int*   senders = (const int*)  d_in[2];
    const int*   recv    = (const int*)  d_in[3];
    const int*   n_node  = (const int*)  d_in[4];
    const float* W_embed = (const float*)d_in[5];
    const float* W_sc_s  = (const float*)d_in[6];
    const float* W_l1_s  = (const float*)d_in[8];
    const float* W_l1_v  = (const float*)d_in[9];
    const float* Wr0     = (const float*)d_in[10];
    const float* Wr1     = (const float*)d_in[11];
    const float* Wr2     = (const float*)d_in[12];
    const float* W_l2_s  = (const float*)d_in[13];
    const float* W_l2_v  = (const float*)d_in[14];
    const float* W_en1   = (const float*)d_in[15];
    const float* W_en2   = (const float*)d_in[16];
    const float* W_mag1  = (const float*)d_in[17];
    const float* W_mag2  = (const float*)d_in[18];
    const float* sc_occ  = (const float*)d_in[19];
    const float* sh_occ  = (const float*)d_in[20];
    const float* esc     = (const float*)d_in[21];
    const float* esh     = (const float*)d_in[22];
    float* out = (float*)d_out;

    static cudaStream_t sA = nullptr, sB = nullptr;
    static cudaEvent_t evF=nullptr, evL1=nullptr, evPack=nullptr,
                       evSCS0=nullptr, evB0=nullptr, evSCS1=nullptr;
    if (sA == nullptr){
        cudaStreamCreateWithFlags(&sA, cudaStreamNonBlocking);
        cudaStreamCreateWithFlags(&sB, cudaStreamNonBlocking);
        cudaEventCreateWithFlags(&evF,    cudaEventDisableTiming);
        cudaEventCreateWithFlags(&evL1,   cudaEventDisableTiming);
        cudaEventCreateWithFlags(&evPack, cudaEventDisableTiming);
        cudaEventCreateWithFlags(&evSCS0, cudaEventDisableTiming);
        cudaEventCreateWithFlags(&evB0,   cudaEventDisableTiming);
        cudaEventCreateWithFlags(&evSCS1, cudaEventDisableTiming);
    }

    // fork
    cudaEventRecord(evF, 0);
    cudaStreamWaitEvent(sA, evF, 0);
    cudaStreamWaitEvent(sB, evF, 0);

    // stream 0: CSR chain + sort/records
    k_zero_init<<<(Nn + 255)/256, 256>>>();
    k_count<<<(Ee + 255)/256, 256>>>(recv);
    k_scan<<<1, 1024>>>();
    k_scatter<<<(Ee + 255)/256, 256>>>(recv);
    k_sortrec<<<SORT_NB, 256>>>(dR, senders);

    // stream A: embed -> l1_s(l0) -> sc_s(l0)
    k_embed<<<(Nn*64 + 255)/256, 256, 0, sA>>>(nodes, W_embed);
    k_l1s0<<<NBs, 256, 0, sA>>>(W_l1_s);
    cudaEventRecord(evL1, sA);
    k_scs<<<NBs, 256, 0, sA>>>(nodes, W_sc_s);           // overlaps gather0
    cudaEventRecord(evSCS0, sA);

    // stream B: radial table -> half2 pack
    k_table<<<TAB_NB, 256, 0, sB>>>(Wr0, Wr1, Wr2);
    k_pack<<<(2*TAB*192 + 255)/256, 256, 0, sB>>>();
    cudaEventRecord(evPack, sB);

    // stream 0: gather0 (needs sortrec (in-order), s1, table)
    cudaStreamWaitEvent(0, evL1, 0);
    cudaStreamWaitEvent(0, evPack, 0);
    k_gather<0><<<(Nn + 7)/8, dim3(32, 8)>>>();

    // phase B layer 0 (needs gather0 + sc_s)
    cudaStreamWaitEvent(0, evSCS0, 0);
    k_phB0<<<NBs + NBv, 256>>>(W_l2_s, W_l2_v);
    cudaEventRecord(evB0, 0);

    // layer 1: l1 group on stream0 -> gather1 ; sc_s(l1) on sA concurrently
    cudaStreamWaitEvent(sA, evB0, 0);
    k_scs<<<NBs, 256, 0, sA>>>(nodes, W_sc_s + 24576);   // overlaps l1grp1+gather1
    cudaEventRecord(evSCS1, sA);

    k_l1grp1<<<NBs + NBv, 256>>>(W_l1_s + 4096, W_l1_v + 1024);
    k_gather<1><<<(Nn + 7)/8, dim3(32, 8)>>>();

    cudaStreamWaitEvent(0, evSCS1, 0);
    k_phB1<<<NBs, 256>>>(W_l2_s + 9216);

    k_head<<<(Nn + 7)/8, dim3(32, 8)>>>(nodes, W_en1, W_en2, W_mag1, W_mag2,
                                        sc_occ, sh_occ, esc, esh, out);
    k_energy<<<Gg, 256>>>(n_node, out);
}

// round 12
// speedup vs baseline: 1.0325x; 1.0325x over previous
#include <cuda_runtime.h>
#include <cuda_fp16.h>
#include <math.h>

#define Nn   20000
#define Ee   320000
#define Gg   16
#define TAB  8192
#define RMAXf 4.0f
#define RINf  3.5f
#define PI_F  3.14159265358979f
#define SQRT3f 1.7320508075688772f
#define INV_SQRT3f 0.5773502691896258f

#define NBs 157   // (Nn+127)/128
#define NBv 469   // (3*Nn+127)/128

// ---------------- device scratch ----------------
__device__ __align__(16) float g_s  [Nn*64];
__device__ __align__(16) float g_v  [Nn*96];     // raw o_v, rows (n*3+c) x 32
__device__ __align__(16) float g_s1 [Nn*64];
__device__ __align__(16) float g_v1 [Nn*96];
__device__ __align__(16) float g_scs[Nn*96];
__device__ __align__(16) float g_as [Nn*96];
__device__ __align__(16) float g_av [Nn*288];
__device__ __align__(16) float g_gate[Nn*32];
__device__ __align__(16) float g_tab [2*(TAB+1)*192];
__device__ __align__(16) __half2 g_tabh[2*TAB*192];
__device__ __align__(16) float4 g_edir[Ee];      // {x, shx, shy, shz}
__device__ int   g_esrc[Ee];
__device__ float g_atomic[Nn];
__device__ int   g_cnt[Nn];
__device__ int   g_off[Nn+1];
__device__ int   g_cur[Nn];
__device__ int   g_elist[Ee];

struct __align__(8) H2x2 { __half2 a, b; };

__device__ __forceinline__ float silu_f(float x){ return x / (1.0f + expf(-x)); }

__device__ __forceinline__ unsigned long long packdup(float a){
    unsigned long long r;
    asm("mov.b64 %0, {%1, %1};" : "=l"(r) : "f"(a));
    return r;
}
__device__ __forceinline__ void unpack2(unsigned long long v, float& lo, float& hi){
    asm("mov.b64 {%0, %1}, %2;" : "=f"(lo), "=f"(hi) : "l"(v));
}
__device__ __forceinline__ void fma2(unsigned long long& d, unsigned long long a, unsigned long long b){
    asm("fma.rn.f32x2 %0, %1, %2, %0;" : "+l"(d) : "l"(a), "l"(b));
}

// ---------------- CSR ----------------
__global__ void k_zero_init(){
    int i = blockIdx.x*256 + threadIdx.x;
    if (i < Nn) g_cnt[i] = 0;
}

__global__ void k_count(const int* __restrict__ recv){
    int e = blockIdx.x*256 + threadIdx.x;
    if (e < Ee) atomicAdd(&g_cnt[recv[e]], 1);
}

__global__ void k_scan(){
    const int PER = 20;
    int t = threadIdx.x;
    int base = t * PER;
    int loc[PER]; int s = 0;
    #pragma unroll
    for (int i = 0; i < PER; i++){
        int idx = base + i;
        int x = (idx < Nn) ? g_cnt[idx] : 0;
        loc[i] = s; s += x;
    }
    int lane = t & 31, wid = t >> 5;
    int v = s;
    #pragma unroll
    for (int o = 1; o < 32; o <<= 1){
        int y = __shfl_up_sync(0xffffffffu, v, o);
        if (lane >= o) v += y;
    }
    __shared__ int wsum[32];
    if (lane == 31) wsum[wid] = v;
    __syncthreads();
    if (wid == 0){
        int w = wsum[lane];
        #pragma unroll
        for (int o = 1; o < 32; o <<= 1){
            int y = __shfl_up_sync(0xffffffffu, w, o);
            if (lane >= o) w += y;
        }
        wsum[lane] = w;
    }
    __syncthreads();
    int excl = v - s + (wid ? wsum[wid-1] : 0);
    #pragma unroll
    for (int i = 0; i < PER; i++){
        int idx = base + i;
        int off = excl + loc[i];
        if (idx < Nn){ g_off[idx] = off; g_cur[idx] = off; }
        else if (idx == Nn) g_off[Nn] = off;
    }
}

__global__ void k_scatter(const int* __restrict__ recv){
    int e = blockIdx.x*256 + threadIdx.x;
    if (e < Ee){
        int p = atomicAdd(&g_cur[recv[e]], 1);
        g_elist[p] = e;
    }
}

// ---------------- sort (smem-staged) + cooperative edge records ----------------
#define SORT_NB  79          // (Nn+255)/256
#define SCAP     5120

__global__ void k_sortrec(const float* __restrict__ dR, const int* __restrict__ senders){
    __shared__ int se[SCAP];
    int blk = blockIdx.x, tid = threadIdx.x;
    int n = blk*256 + tid;
    int n0 = blk*256;
    int n1 = n0 + 256; if (n1 > Nn) n1 = Nn;
    int p0 = g_off[n0], p1 = g_off[n1];
    int cnt = p1 - p0;
    if (cnt <= SCAP){
        for (int i = tid; i < cnt; i += 256) se[i] = g_elist[p0 + i];
        __syncthreads();
        if (n < Nn){
            int b = g_off[n] - p0, e2 = g_off[n+1] - p0;
            for (int i = b+1; i < e2; i++){
                int key = se[i];
                int j = i-1;
                while (j >= b && se[j] > key){ se[j+1] = se[j]; j--; }
                se[j+1] = key;
            }
        }
        __syncthreads();
        for (int p = p0 + tid; p < p1; p += 256){
            int e = se[p - p0];
            float dx = dR[3*e+0], dy = dR[3*e+1], dz = dR[3*e+2];
            float r = sqrtf(dx*dx + dy*dy + dz*dz);
            float inv = 1.0f / fmaxf(r, 1e-6f);
            float x = fminf(r * ((float)TAB / RMAXf), (float)TAB);
            g_edir[p] = make_float4(x, SQRT3f*dx*inv, SQRT3f*dy*inv, SQRT3f*dz*inv);
            g_esrc[p] = senders[e];
        }
    } else {
        if (n < Nn){
            int b = g_off[n], e2 = g_off[n+1];
            for (int i = b+1; i < e2; i++){
                int key = g_elist[i];
                int j = i-1;
                while (j >= b && g_elist[j] > key){ g_elist[j+1] = g_elist[j]; j--; }
                g_elist[j+1] = key;
            }
        }
        __syncthreads();
        for (int p = p0 + tid; p < p1; p += 256){
            int e = g_elist[p];
            float dx = dR[3*e+0], dy = dR[3*e+1], dz = dR[3*e+2];
            float r = sqrtf(dx*dx + dy*dy + dz*dz);
            float inv = 1.0f / fmaxf(r, 1e-6f);
            float x = fminf(r * ((float)TAB / RMAXf), (float)TAB);
            g_edir[p] = make_float4(x, SQRT3f*dx*inv, SQRT3f*dy*inv, SQRT3f*dz*inv);
            g_esrc[p] = senders[e];
        }
    }
}

// ---------------- embedding ----------------
__global__ void k_embed(const float* __restrict__ nodes, const float* __restrict__ Wemb){
    int idx = blockIdx.x*256 + threadIdx.x;
    if (idx >= Nn*64) return;
    int n = idx >> 6, o = idx & 63;
    float acc = 0.f;
    #pragma unroll
    for (int e = 0; e < 4; e++) acc = fmaf(nodes[n*4+e], Wemb[e*64+o], acc);
    g_s[idx] = acc * 0.5f;
}

// ---------------- radial table ----------------
#define TROWS    (2*(TAB+1))
#define TAB_NB   ((TROWS+3)/4)

__global__ void k_table(const float* __restrict__ Wr0, const float* __restrict__ Wr1,
                        const float* __restrict__ Wr2){
    __shared__ float h1s[4][64];
    __shared__ float h2s[4][64];
    int tid = threadIdx.x;
    int q = blockIdx.x*4 + (tid >> 6);
    int t = tid & 63, sub = tid >> 6;
    bool act = (q < TROWS);
    int l = act ? q / (TAB+1) : 0;
    int row = act ? q % (TAB+1) : 0;
    const float* R0 = Wr0 + l*512;
    const float* R1 = Wr1 + l*4096;
    const float* R2 = Wr2 + l*12288;
    float r = (float)row * (RMAXf / (float)TAB);
    float rs = fmaxf(r, 1e-6f);
    float env;
    if (r < RINf) env = 1.0f;
    else if (r > RMAXf) env = 0.0f;
    else { float tt = (r - RINf) / (RMAXf - RINf); env = 0.5f*(cosf(PI_F*tt)+1.0f); }
    float remb[8];
    #pragma unroll
    for (int nb = 1; nb <= 8; nb++)
        remb[nb-1] = 0.70710678f * sinf((float)nb * PI_F * rs / RMAXf) / rs * env;
    float h = 0.f;
    #pragma unroll
    for (int k = 0; k < 8; k++) h = fmaf(remb[k], R0[k*64+t], h);
    h1s[sub][t] = silu_f(h * 0.35355339f);
    __syncthreads();
    float h2 = 0.f;
    #pragma unroll
    for (int k = 0; k < 64; k++) h2 = fmaf(h1s[sub][k], R1[k*64+t], h2);
    h2s[sub][t] = silu_f(h2 * 0.125f);
    __syncthreads();
    if (act){
        #pragma unroll
        for (int j = 0; j < 3; j++){
            int o = t + 64*j;
            float w = 0.f;
            #pragma unroll 8
            for (int k = 0; k < 64; k++) w = fmaf(h2s[sub][k], R2[k*192+o], w);
            g_tab[q*192 + o] = w * 0.125f;
        }
    }
}

__global__ void k_pack(){
    int idx = blockIdx.x*256 + threadIdx.x;
    if (idx >= 2*TAB*192) return;
    int l   = idx / (TAB*192);
    int rem = idx % (TAB*192);
    int row = rem / 192, o = rem % 192;
    float v0 = g_tab[(l*(TAB+1) + row    )*192 + o];
    float v1 = g_tab[(l*(TAB+1) + row + 1)*192 + o];
    g_tabh[idx] = __floats2half2_rn(v0, v1 - v0);
}

// ---------------- gemm body (f32x2 packed, 8 contiguous rows/thread) ----------------
#define AS_STRIDE 132
template<int K, int NC, int MODE, int ASTRIDE>
__device__ __forceinline__ void gemm_body(float* sm,
            const float* __restrict__ A, const float* __restrict__ B,
            const float* __restrict__ D, float* __restrict__ C,
            const float* __restrict__ attrs, int M, float alpha, int blk){
    constexpr int TN = NC / 16;
    constexpr int TH = TN / 2;
    float* As = sm;                    // [16][AS_STRIDE]
    float* Bs = sm + 16*AS_STRIDE;     // [16][NC]
    int tid = threadIdx.x;
    int mg = tid & 15, ng = tid >> 4;
    int m0 = blk * 128;
    unsigned long long acc2[8][TH];
    #pragma unroll
    for (int i = 0; i < 8; i++)
        #pragma unroll
        for (int j = 0; j < TH; j++) acc2[i][j] = 0ull;

    for (int kc = 0; kc < K; kc += 16){
        #pragma unroll
        for (int q = 0; q < 8; q++){
            int e2 = q*256 + tid;
            int r = e2 >> 4, c = e2 & 15;
            int row = m0 + r;
            float val = 0.f;
            if (row < M){
                int k = kc + c;
                if (MODE == 1)      val = A[row*64 + (k>>2)] * attrs[row*4 + (k&3)];
                else if (MODE == 5) val = A[row*32 + k] * attrs[(row/3)*32 + k];
                else                val = A[row*ASTRIDE + k];
            }
            As[c*AS_STRIDE + r] = val;
        }
        for (int e2 = tid; e2 < 16*NC; e2 += 256){
            int r = e2 / NC, c = e2 % NC;
            Bs[r*NC + c] = B[(kc+r)*NC + c];
        }
        __syncthreads();
        #pragma unroll
        for (int kk = 0; kk < 16; kk++){
            const float4* ap = (const float4*)(As + kk*AS_STRIDE + mg*8);
            float4 a0 = ap[0], a1 = ap[1];
            float aa[8] = {a0.x, a0.y, a0.z, a0.w, a1.x, a1.y, a1.z, a1.w};
            unsigned long long aa2[8];
            #pragma unroll
            for (int i = 0; i < 8; i++) aa2[i] = packdup(aa[i]);
            const unsigned long long* bp =
                (const unsigned long long*)(Bs + kk*NC + ng*TN);
            unsigned long long bb2[TH];
            #pragma unroll
            for (int j = 0; j < TH; j++) bb2[j] = bp[j];
            #pragma unroll
            for (int i = 0; i < 8; i++)
                #pragma unroll
                for (int j = 0; j < TH; j++) fma2(acc2[i][j], aa2[i], bb2[j]);
        }
        __syncthreads();
    }
    #pragma unroll
    for (int i = 0; i < 8; i++){
        int row = m0 + mg*8 + i;
        if (row >= M) continue;
        #pragma unroll
        for (int j = 0; j < TH; j++){
            float vlo, vhi;
            unpack2(acc2[i][j], vlo, vhi);
            int col = ng*TN + 2*j;
            float val0 = vlo * alpha;
            float val1 = vhi * alpha;
            if (MODE == 2){
                val0 += D[row*96 + col];
                val1 += D[row*96 + col + 1];
                float sv0 = silu_f(val0);
                float sv1 = silu_f(val1);
                if (col < 64){
                    g_s[row*64 + col]   = sv0;
                    g_s[row*64 + col+1] = sv1;
                } else {
                    g_gate[row*32 + (col-64)]   = sv0;
                    g_gate[row*32 + (col-64)+1] = sv1;
                }
            } else {
                C[row*NC + col]   = val0;
                C[row*NC + col+1] = val1;
            }
        }
    }
}

#define A_SCS 0.0625f
#define A_S1  0.125f
#define A_V1  0.17677669529f
#define A_O   0.10206207262f

#define SM_FLOATS (16*AS_STRIDE + 16*96)

// phase A, layer 0: sc_s | l1_s
__global__ __launch_bounds__(256, 2)
void k_phA0(const float* __restrict__ nodes, const float* __restrict__ WscS,
            const float* __restrict__ Wl1s){
    __shared__ __align__(16) float sm[SM_FLOATS];
    int b = blockIdx.x;
    if (b < NBs) gemm_body<256,96,1,256>(sm, g_s, WscS, nullptr, g_scs, nodes, Nn, A_SCS, b);
    else         gemm_body< 64,64,0, 64>(sm, g_s, Wl1s, nullptr, g_s1, nullptr, Nn, A_S1, b-NBs);
}

// phase A, layer 1: sc_s | l1_s | gated l1_v
__global__ __launch_bounds__(256, 2)
void k_phA1(const float* __restrict__ nodes, const float* __restrict__ WscS,
            const float* __restrict__ Wl1s, const float* __restrict__ Wl1v){
    __shared__ __align__(16) float sm[SM_FLOATS];
    int b = blockIdx.x;
    if (b < NBs)        gemm_body<256,96,1,256>(sm, g_s, WscS, nullptr, g_scs, nodes, Nn, A_SCS, b);
    else if (b < 2*NBs) gemm_body< 64,64,0, 64>(sm, g_s, Wl1s, nullptr, g_s1, nullptr, Nn, A_S1, b-NBs);
    else                gemm_body< 32,32,5, 32>(sm, g_v, Wl1v, nullptr, g_v1, g_gate, 3*Nn, A_V1, b-2*NBs);
}

// phase B, layer 0: l2_s (K=64 effective) | l2_v (K=64 effective)
__global__ __launch_bounds__(256, 2)
void k_phB0(const float* __restrict__ Wl2s, const float* __restrict__ Wl2v){
    __shared__ __align__(16) float sm[SM_FLOATS];
    int b = blockIdx.x;
    if (b < NBs) gemm_body<64,96,2,96>(sm, g_as, Wl2s, g_scs, nullptr, nullptr, Nn, A_O, b);
    else         gemm_body<64,32,0,96>(sm, g_av, Wl2v, nullptr, g_v, nullptr, 3*Nn, A_O, b-NBs);
}

// phase B, layer 1: l2_s only (full K=96)
__global__ __launch_bounds__(256, 2)
void k_phB1(const float* __restrict__ Wl2s){
    __shared__ __align__(16) float sm[SM_FLOATS];
    gemm_body<96,96,2,96>(sm, g_as, Wl2s, g_scs, nullptr, nullptr, Nn, A_O, blockIdx.x);
}

// ---------------- gather (lane l owns features 2l, 2l+1) ----------------
template<int LAYER>
__global__ void k_gather(){
    int n = blockIdx.x*8 + threadIdx.y;
    if (n >= Nn) return;
    int l = threadIdx.x;
    const __half2* tb_base = g_tabh + LAYER*(TAB*192);
    int beg = g_off[n], end = g_off[n+1];
    float as0 = 0.f, as1 = 0.f, as2 = 0.f;
    float av00=0,av01=0, av10=0,av11=0, av20=0,av21=0;
    for (int p = beg; p < end; p++){
        float4 d = g_edir[p];
        int src = g_esrc[p];
        int gi = (int)d.x; gi = min(gi, TAB-1);
        float f = d.x - (float)gi;
        const __half2* t0 = tb_base + gi*192;
        H2x2 w1 = *reinterpret_cast<const H2x2*>(t0 + 2*l);
        float w1a = __low2float(w1.a) + f*__high2float(w1.a);
        float w1b = __low2float(w1.b) + f*__high2float(w1.b);
        float2 se = *reinterpret_cast<const float2*>(&g_s1[src*64 + 2*l]);
        as0 = fmaf(w1a, se.x, as0);
        as1 = fmaf(w1b, se.y, as1);
        if (LAYER == 0){
            H2x2 w2 = *reinterpret_cast<const H2x2*>(t0 + 64 + 2*l);
            float w2a = __low2float(w2.a) + f*__high2float(w2.a);
            float w2b = __low2float(w2.b) + f*__high2float(w2.b);
            float p2a = w2a*se.x, p2b = w2b*se.y;
            av00 = fmaf(p2a, d.y, av00); av10 = fmaf(p2a, d.z, av10); av20 = fmaf(p2a, d.w, av20);
            av01 = fmaf(p2b, d.y, av01); av11 = fmaf(p2b, d.z, av11); av21 = fmaf(p2b, d.w, av21);
        } else {
            __half2 h4 = t0[160 + l];
            float w4 = __low2float(h4) + f*__high2float(h4);
            float ve0 = g_v1[src*96 +      l];
            float ve1 = g_v1[src*96 + 32 + l];
            float ve2 = g_v1[src*96 + 64 + l];
            float dv = ve0*d.y + ve1*d.z + ve2*d.w;
            as2 = fmaf(w4*INV_SQRT3f, dv, as2);
        }
    }
    const float sc = 0.25f;
    *reinterpret_cast<float2*>(&g_as[n*96 + 2*l]) = make_float2(as0*sc, as1*sc);
    if (LAYER == 0){
        int b0 = n*288;
        *reinterpret_cast<float2*>(&g_av[b0 +       2*l]) = make_float2(av00*sc, av01*sc);
        *reinterpret_cast<float2*>(&g_av[b0 +  96 + 2*l]) = make_float2(av10*sc, av11*sc);
        *reinterpret_cast<float2*>(&g_av[b0 + 192 + 2*l]) = make_float2(av20*sc, av21*sc);
    } else {
        g_as[n*96 + 64 + l] = as2*sc;
    }
}

// ---------------- heads ----------------
__global__ void k_head(const float* __restrict__ nodes,
                       const float* __restrict__ Wen1, const float* __restrict__ Wen2,
                       const float* __restrict__ Wmag1, const float* __restrict__ Wmag2,
                       const float* __restrict__ sc_occ, const float* __restrict__ sh_occ,
                       const float* __restrict__ esc, const float* __restrict__ esh,
                       float* __restrict__ out){
    int n = blockIdx.x*8 + threadIdx.y;
    if (n >= Nn) return;
    int t = threadIdx.x;
    const float* s = g_s + n*64;
    float he = 0.f, hm = 0.f;
    #pragma unroll 8
    for (int i = 0; i < 64; i++){
        float si = s[i];
        he = fmaf(si, Wen1[i*32+t], he);
        hm = fmaf(si, Wmag1[i*32+t], hm);
    }
    he *= 0.125f; hm *= 0.125f;
    float pe  = he * Wen2[t];
    float pm0 = hm * Wmag2[t*2+0];
    float pm1 = hm * Wmag2[t*2+1];
    #pragma unroll
    for (int o = 16; o; o >>= 1){
        pe  += __shfl_down_sync(0xffffffffu, pe,  o);
        pm0 += __shfl_down_sync(0xffffffffu, pm0, o);
        pm1 += __shfl_down_sync(0xffffffffu, pm1, o);
    }
    if (t == 0){
        g_atomic[n] = esc[0] * (pe * 0.17677669529f) + esh[0];
        float a0 = nodes[n*4+0], a1 = nodes[n*4+1], a2 = nodes[n*4+2];
        float s0 = a0*sc_occ[0] + a1*sc_occ[2] + a2*sc_occ[4];
        float s1m= a0*sc_occ[1] + a1*sc_occ[3] + a2*sc_occ[5];
        float t0 = a0*sh_occ[0] + a1*sh_occ[2] + a2*sh_occ[4];
        float t1 = a0*sh_occ[1] + a1*sh_occ[3] + a2*sh_occ[5];
        out[Gg + n*2 + 0] = s0 *(pm0 * 0.17677669529f) + t0;
        out[Gg + n*2 + 1] = s1m*(pm1 * 0.17677669529f) + t1;
    }
}

__global__ void k_energy(const int* __restrict__ n_node, float* __restrict__ out){
    __shared__ float sm[256];
    int g = blockIdx.x, t = threadIdx.x;
    int start = 0;
    for (int q = 0; q < g; q++) start += n_node[q];
    int end = start + n_node[g];
    if (start > Nn) start = Nn;
    if (end > Nn) end = Nn;
    float acc = 0.f;
    for (int i = start + t; i < end; i += 256) acc += g_atomic[i];
    sm[t] = acc; __syncthreads();
    #pragma unroll
    for (int o = 128; o; o >>= 1){ if (t < o) sm[t] += sm[t+o]; __syncthreads(); }
    if (t == 0) out[g] = sm[0];
}

// ---------------- launch ----------------
extern "C" void kernel_launch(void* const* d_in, const int* in_sizes, int n_in,
                              void* d_out, int out_size){
    const float* nodes   = (const float*)d_in[0];
    const float* dR      = (const float*)d_in[1];
    const int*   senders = (const int*)  d_in[2];
    const int*   recv    = (const int*)  d_in[3];
    const int*   n_node  = (const int*)  d_in[4];
    const float* W_embed = (const float*)d_in[5];
    const float* W_sc_s  = (const float*)d_in[6];
    const float* W_l1_s  = (const float*)d_in[8];
    const float* W_l1_v  = (const float*)d_in[9];
    const float* Wr0     = (const float*)d_in[10];
    const float* Wr1     = (const float*)d_in[11];
    const float* Wr2     = (const float*)d_in[12];
    const float* W_l2_s  = (const float*)d_in[13];
    const float* W_l2_v  = (const float*)d_in[14];
    const float* W_en1   = (const float*)d_in[15];
    const float* W_en2   = (const float*)d_in[16];
    const float* W_mag1  = (const float*)d_in[17];
    const float* W_mag2  = (const float*)d_in[18];
    const float* sc_occ  = (const float*)d_in[19];
    const float* sh_occ  = (const float*)d_in[20];
    const float* esc     = (const float*)d_in[21];
    const float* esh     = (const float*)d_in[22];
    float* out = (float*)d_out;

    static cudaStream_t sA = nullptr, sB = nullptr;
    static cudaEvent_t evF = nullptr, evA = nullptr, evB = nullptr;
    if (sA == nullptr){
        cudaStreamCreateWithFlags(&sA, cudaStreamNonBlocking);
        cudaStreamCreateWithFlags(&sB, cudaStreamNonBlocking);
        cudaEventCreateWithFlags(&evF, cudaEventDisableTiming);
        cudaEventCreateWithFlags(&evA, cudaEventDisableTiming);
        cudaEventCreateWithFlags(&evB, cudaEventDisableTiming);
    }

    // fork
    cudaEventRecord(evF, 0);
    cudaStreamWaitEvent(sA, evF, 0);
    cudaStreamWaitEvent(sB, evF, 0);

    // stream 0: CSR chain + sort/records
    k_zero_init<<<(Nn + 255)/256, 256>>>();
    k_count<<<(Ee + 255)/256, 256>>>(recv);
    k_scan<<<1, 1024>>>();
    k_scatter<<<(Ee + 255)/256, 256>>>(recv);
    k_sortrec<<<SORT_NB, 256>>>(dR, senders);

    // stream A: embed -> phase A layer 0
    k_embed<<<(Nn*64 + 255)/256, 256, 0, sA>>>(nodes, W_embed);
    k_phA0<<<2*NBs, 256, 0, sA>>>(nodes, W_sc_s, W_l1_s);

    // stream B: radial table -> half2 pack
    k_table<<<TAB_NB, 256, 0, sB>>>(Wr0, Wr1, Wr2);
    k_pack<<<(2*TAB*192 + 255)/256, 256, 0, sB>>>();

    // join
    cudaEventRecord(evA, sA);
    cudaEventRecord(evB, sB);
    cudaStreamWaitEvent(0, evA, 0);
    cudaStreamWaitEvent(0, evB, 0);

    // layer 0 tail
    k_gather<0><<<(Nn + 7)/8, dim3(32, 8)>>>();
    k_phB0<<<NBs + NBv, 256>>>(W_l2_s, W_l2_v);
    // layer 1
    k_phA1<<<2*NBs + NBv, 256>>>(nodes, W_sc_s + 24576, W_l1_s + 4096, W_l1_v + 1024);
    k_gather<1><<<(Nn + 7)/8, dim3(32, 8)>>>();
    k_phB1<<<NBs, 256>>>(W_l2_s + 9216);

    k_head<<<(Nn + 7)/8, dim3(32, 8)>>>(nodes, W_en1, W_en2, W_mag1, W_mag2,
                                        sc_occ, sh_occ, esc, esh, out);
    k_energy<<<Gg, 256>>>(n_node, out);
}

// round 13
// speedup vs baseline: 1.1999x; 1.1621x over previous
#include <cuda_runtime.h>
#include <cuda_fp16.h>
#include <math.h>

#define Nn   20000
#define Ee   320000
#define Gg   16
#define TAB  8192
#define RMAXf 4.0f
#define RINf  3.5f
#define PI_F  3.14159265358979f
#define SQRT3f 1.7320508075688772f
#define INV_SQRT3f 0.5773502691896258f

#define NBs 157   // (Nn+127)/128
#define NBv 469   // (3*Nn+127)/128

// ---------------- device scratch ----------------
__device__ __align__(16) float g_s  [Nn*64];
__device__ __align__(16) float g_v  [Nn*96];     // raw o_v, rows (n*3+c) x 32
__device__ __align__(16) float g_s1 [Nn*64];
__device__ __align__(16) float g_v1 [Nn*96];
__device__ __align__(16) float g_scs[Nn*96];
__device__ __align__(16) float g_as [Nn*96];
__device__ __align__(16) float g_av [Nn*288];
__device__ __align__(16) float g_gate[Nn*32];
__device__ __align__(16) float g_tab [2*(TAB+1)*192];
__device__ __align__(16) __half2 g_tabh[2*TAB*192];
__device__ __align__(16) float4 g_edir[Ee];      // {x, shx, shy, shz}
__device__ int   g_esrc[Ee];
__device__ float g_atomic[Nn];
__device__ int   g_cnt[Nn];
__device__ int   g_off[Nn+1];
__device__ int   g_cur[Nn];
__device__ int   g_elist[Ee];

struct __align__(8) H2x2 { __half2 a, b; };

__device__ __forceinline__ float silu_f(float x){ return x / (1.0f + expf(-x)); }

__device__ __forceinline__ unsigned long long packdup(float a){
    unsigned long long r;
    asm("mov.b64 %0, {%1, %1};" : "=l"(r) : "f"(a));
    return r;
}
__device__ __forceinline__ void unpack2(unsigned long long v, float& lo, float& hi){
    asm("mov.b64 {%0, %1}, %2;" : "=f"(lo), "=f"(hi) : "l"(v));
}
__device__ __forceinline__ void fma2(unsigned long long& d, unsigned long long a, unsigned long long b){
    asm("fma.rn.f32x2 %0, %1, %2, %0;" : "+l"(d) : "l"(a), "l"(b));
}

// ---------------- CSR ----------------
__global__ void k_zero_init(){
    int i = blockIdx.x*256 + threadIdx.x;
    if (i < Nn) g_cnt[i] = 0;
}

__global__ void k_count(const int* __restrict__ recv){
    int e = blockIdx.x*256 + threadIdx.x;
    if (e < Ee) atomicAdd(&g_cnt[recv[e]], 1);
}

__global__ void k_scan(){
    const int PER = 20;
    int t = threadIdx.x;
    int base = t * PER;
    int loc[PER]; int s = 0;
    #pragma unroll
    for (int i = 0; i < PER; i++){
        int idx = base + i;
        int x = (idx < Nn) ? g_cnt[idx] : 0;
        loc[i] = s; s += x;
    }
    int lane = t & 31, wid = t >> 5;
    int v = s;
    #pragma unroll
    for (int o = 1; o < 32; o <<= 1){
        int y = __shfl_up_sync(0xffffffffu, v, o);
        if (lane >= o) v += y;
    }
    __shared__ int wsum[32];
    if (lane == 31) wsum[wid] = v;
    __syncthreads();
    if (wid == 0){
        int w = wsum[lane];
        #pragma unroll
        for (int o = 1; o < 32; o <<= 1){
            int y = __shfl_up_sync(0xffffffffu, w, o);
            if (lane >= o) w += y;
        }
        wsum[lane] = w;
    }
    __syncthreads();
    int excl = v - s + (wid ? wsum[wid-1] : 0);
    #pragma unroll
    for (int i = 0; i < PER; i++){
        int idx = base + i;
        int off = excl + loc[i];
        if (idx < Nn){ g_off[idx] = off; g_cur[idx] = off; }
        else if (idx == Nn) g_off[Nn] = off;
    }
}

__global__ void k_scatter(const int* __restrict__ recv){
    int e = blockIdx.x*256 + threadIdx.x;
    if (e < Ee){
        int p = atomicAdd(&g_cur[recv[e]], 1);
        g_elist[p] = e;
    }
}

// ---------------- sort (L1-resident global) + cooperative edge records ----------------
#define SORT_NB  79          // (Nn+255)/256

__global__ void k_sortrec(const float* __restrict__ dR, const int* __restrict__ senders){
    int blk = blockIdx.x, tid = threadIdx.x;
    int n = blk*256 + tid;
    if (n < Nn){
        int b = g_off[n], e2 = g_off[n+1];
        for (int i = b+1; i < e2; i++){
            int key = g_elist[i];
            int j = i-1;
            while (j >= b && g_elist[j] > key){ g_elist[j+1] = g_elist[j]; j--; }
            g_elist[j+1] = key;
        }
    }
    __syncthreads();
    int n0 = blk*256;
    int n1 = n0 + 256; if (n1 > Nn) n1 = Nn;
    int p0 = g_off[n0], p1 = g_off[n1];
    for (int p = p0 + tid; p < p1; p += 256){
        int e = g_elist[p];
        float dx = dR[3*e+0], dy = dR[3*e+1], dz = dR[3*e+2];
        float r = sqrtf(dx*dx + dy*dy + dz*dz);
        float inv = 1.0f / fmaxf(r, 1e-6f);
        float x = fminf(r * ((float)TAB / RMAXf), (float)TAB);
        g_edir[p] = make_float4(x, SQRT3f*dx*inv, SQRT3f*dy*inv, SQRT3f*dz*inv);
        g_esrc[p] = senders[e];
    }
}

// ---------------- embedding ----------------
__global__ void k_embed(const float* __restrict__ nodes, const float* __restrict__ Wemb){
    int idx = blockIdx.x*256 + threadIdx.x;
    if (idx >= Nn*64) return;
    int n = idx >> 6, o = idx & 63;
    float acc = 0.f;
    #pragma unroll
    for (int e = 0; e < 4; e++) acc = fmaf(nodes[n*4+e], Wemb[e*64+o], acc);
    g_s[idx] = acc * 0.5f;
}

// ---------------- radial table ----------------
#define TROWS    (2*(TAB+1))
#define TAB_NB   ((TROWS+3)/4)

__global__ void k_table(const float* __restrict__ Wr0, const float* __restrict__ Wr1,
                        const float* __restrict__ Wr2){
    __shared__ float h1s[4][64];
    __shared__ float h2s[4][64];
    int tid = threadIdx.x;
    int q = blockIdx.x*4 + (tid >> 6);
    int t = tid & 63, sub = tid >> 6;
    bool act = (q < TROWS);
    int l = act ? q / (TAB+1) : 0;
    int row = act ? q % (TAB+1) : 0;
    const float* R0 = Wr0 + l*512;
    const float* R1 = Wr1 + l*4096;
    const float* R2 = Wr2 + l*12288;
    float r = (float)row * (RMAXf / (float)TAB);
    float rs = fmaxf(r, 1e-6f);
    float env;
    if (r < RINf) env = 1.0f;
    else if (r > RMAXf) env = 0.0f;
    else { float tt = (r - RINf) / (RMAXf - RINf); env = 0.5f*(cosf(PI_F*tt)+1.0f); }
    float remb[8];
    #pragma unroll
    for (int nb = 1; nb <= 8; nb++)
        remb[nb-1] = 0.70710678f * sinf((float)nb * PI_F * rs / RMAXf) / rs * env;
    float h = 0.f;
    #pragma unroll
    for (int k = 0; k < 8; k++) h = fmaf(remb[k], R0[k*64+t], h);
    h1s[sub][t] = silu_f(h * 0.35355339f);
    __syncthreads();
    float h2 = 0.f;
    #pragma unroll
    for (int k = 0; k < 64; k++) h2 = fmaf(h1s[sub][k], R1[k*64+t], h2);
    h2s[sub][t] = silu_f(h2 * 0.125f);
    __syncthreads();
    if (act){
        #pragma unroll
        for (int j = 0; j < 3; j++){
            int o = t + 64*j;
            float w = 0.f;
            #pragma unroll 8
            for (int k = 0; k < 64; k++) w = fmaf(h2s[sub][k], R2[k*192+o], w);
            g_tab[q*192 + o] = w * 0.125f;
        }
    }
}

__global__ void k_pack(){
    int idx = blockIdx.x*256 + threadIdx.x;
    if (idx >= 2*TAB*192) return;
    int l   = idx / (TAB*192);
    int rem = idx % (TAB*192);
    int row = rem / 192, o = rem % 192;
    float v0 = g_tab[(l*(TAB+1) + row    )*192 + o];
    float v1 = g_tab[(l*(TAB+1) + row + 1)*192 + o];
    g_tabh[idx] = __floats2half2_rn(v0, v1 - v0);
}

// ---------------- gemm body (f32x2, 32-wide k-chunks, 8 contiguous rows/thread) ----------------
#define AS_STRIDE 132
template<int K, int NC, int MODE, int ASTRIDE>
__device__ __forceinline__ void gemm_body(float* sm,
            const float* __restrict__ A, const float* __restrict__ B,
            const float* __restrict__ D, float* __restrict__ C,
            const float* __restrict__ attrs, int M, float alpha, int blk){
    constexpr int TN = NC / 16;
    constexpr int TH = TN / 2;
    float* As = sm;                    // [32][AS_STRIDE]
    float* Bs = sm + 32*AS_STRIDE;     // [32][NC]
    int tid = threadIdx.x;
    int mg = tid & 15, ng = tid >> 4;
    int m0 = blk * 128;
    unsigned long long acc2[8][TH];
    #pragma unroll
    for (int i = 0; i < 8; i++)
        #pragma unroll
        for (int j = 0; j < TH; j++) acc2[i][j] = 0ull;

    for (int kc = 0; kc < K; kc += 32){
        #pragma unroll
        for (int q = 0; q < 16; q++){
            int e2 = q*256 + tid;
            int r = e2 >> 5, c = e2 & 31;      // full 128B line per row per warp
            int row = m0 + r;
            float val = 0.f;
            if (row < M){
                int k = kc + c;
                if (MODE == 1)      val = A[row*64 + (k>>2)] * attrs[row*4 + (k&3)];
                else if (MODE == 5) val = A[row*32 + k] * attrs[(row/3)*32 + k];
                else                val = A[row*ASTRIDE + k];
            }
            As[c*AS_STRIDE + r] = val;
        }
        for (int e2 = tid; e2 < 32*NC; e2 += 256){
            int r = e2 / NC, c = e2 % NC;
            Bs[r*NC + c] = B[(kc+r)*NC + c];
        }
        __syncthreads();
        #pragma unroll
        for (int kk = 0; kk < 32; kk++){
            const float4* ap = (const float4*)(As + kk*AS_STRIDE + mg*8);
            float4 a0 = ap[0], a1 = ap[1];
            float aa[8] = {a0.x, a0.y, a0.z, a0.w, a1.x, a1.y, a1.z, a1.w};
            unsigned long long aa2[8];
            #pragma unroll
            for (int i = 0; i < 8; i++) aa2[i] = packdup(aa[i]);
            const unsigned long long* bp =
                (const unsigned long long*)(Bs + kk*NC + ng*TN);
            unsigned long long bb2[TH];
            #pragma unroll
            for (int j = 0; j < TH; j++) bb2[j] = bp[j];
            #pragma unroll
            for (int i = 0; i < 8; i++)
                #pragma unroll
                for (int j = 0; j < TH; j++) fma2(acc2[i][j], aa2[i], bb2[j]);
        }
        __syncthreads();
    }
    #pragma unroll
    for (int i = 0; i < 8; i++){
        int row = m0 + mg*8 + i;
        if (row >= M) continue;
        #pragma unroll
        for (int j = 0; j < TH; j++){
            float vlo, vhi;
            unpack2(acc2[i][j], vlo, vhi);
            int col = ng*TN + 2*j;
            float val0 = vlo * alpha;
            float val1 = vhi * alpha;
            if (MODE == 2){
                val0 += D[row*96 + col];
                val1 += D[row*96 + col + 1];
                float sv0 = silu_f(val0);
                float sv1 = silu_f(val1);
                if (col < 64){
                    g_s[row*64 + col]   = sv0;
                    g_s[row*64 + col+1] = sv1;
                } else {
                    g_gate[row*32 + (col-64)]   = sv0;
                    g_gate[row*32 + (col-64)+1] = sv1;
                }
            } else {
                C[row*NC + col]   = val0;
                C[row*NC + col+1] = val1;
            }
        }
    }
}

#define A_SCS 0.0625f
#define A_S1  0.125f
#define A_V1  0.17677669529f
#define A_O   0.10206207262f

#define SM_FLOATS (32*AS_STRIDE + 32*96)

// phase A, layer 0: sc_s | l1_s
__global__ __launch_bounds__(256, 2)
void k_phA0(const float* __restrict__ nodes, const float* __restrict__ WscS,
            const float* __restrict__ Wl1s){
    __shared__ __align__(16) float sm[SM_FLOATS];
    int b = blockIdx.x;
    if (b < NBs) gemm_body<256,96,1,256>(sm, g_s, WscS, nullptr, g_scs, nodes, Nn, A_SCS, b);
    else         gemm_body< 64,64,0, 64>(sm, g_s, Wl1s, nullptr, g_s1, nullptr, Nn, A_S1, b-NBs);
}

// phase A, layer 1: sc_s | l1_s | gated l1_v
__global__ __launch_bounds__(256, 2)
void k_phA1(const float* __restrict__ nodes, const float* __restrict__ WscS,
            const float* __restrict__ Wl1s, const float* __restrict__ Wl1v){
    __shared__ __align__(16) float sm[SM_FLOATS];
    int b = blockIdx.x;
    if (b < NBs)        gemm_body<256,96,1,256>(sm, g_s, WscS, nullptr, g_scs, nodes, Nn, A_SCS, b);
    else if (b < 2*NBs) gemm_body< 64,64,0, 64>(sm, g_s, Wl1s, nullptr, g_s1, nullptr, Nn, A_S1, b-NBs);
    else                gemm_body< 32,32,5, 32>(sm, g_v, Wl1v, nullptr, g_v1, g_gate, 3*Nn, A_V1, b-2*NBs);
}

// phase B, layer 0: l2_s (K=64 effective) | l2_v (K=64 effective)
__global__ __launch_bounds__(256, 2)
void k_phB0(const float* __restrict__ Wl2s, const float* __restrict__ Wl2v){
    __shared__ __align__(16) float sm[SM_FLOATS];
    int b = blockIdx.x;
    if (b < NBs) gemm_body<64,96,2,96>(sm, g_as, Wl2s, g_scs, nullptr, nullptr, Nn, A_O, b);
    else         gemm_body<64,32,0,96>(sm, g_av, Wl2v, nullptr, g_v, nullptr, 3*Nn, A_O, b-NBs);
}

// phase B, layer 1: l2_s only (full K=96)
__global__ __launch_bounds__(256, 2)
void k_phB1(const float* __restrict__ Wl2s){
    __shared__ __align__(16) float sm[SM_FLOATS];
    gemm_body<96,96,2,96>(sm, g_as, Wl2s, g_scs, nullptr, nullptr, Nn, A_O, blockIdx.x);
}

// ---------------- gather (lane l owns features 2l, 2l+1) ----------------
template<int LAYER>
__global__ void k_gather(){
    int n = blockIdx.x*8 + threadIdx.y;
    if (n >= Nn) return;
    int l = threadIdx.x;
    const __half2* tb_base = g_tabh + LAYER*(TAB*192);
    int beg = g_off[n], end = g_off[n+1];
    float as0 = 0.f, as1 = 0.f, as2 = 0.f;
    float av00=0,av01=0, av10=0,av11=0, av20=0,av21=0;
    #pragma unroll 2
    for (int p = beg; p < end; p++){
        float4 d = g_edir[p];
        int src = g_esrc[p];
        int gi = (int)d.x; gi = min(gi, TAB-1);
        float f = d.x - (float)gi;
        const __half2* t0 = tb_base + gi*192;
        H2x2 w1 = *reinterpret_cast<const H2x2*>(t0 + 2*l);
        float w1a = __low2float(w1.a) + f*__high2float(w1.a);
        float w1b = __low2float(w1.b) + f*__high2float(w1.b);
        float2 se = *reinterpret_cast<const float2*>(&g_s1[src*64 + 2*l]);
        as0 = fmaf(w1a, se.x, as0);
        as1 = fmaf(w1b, se.y, as1);
        if (LAYER == 0){
            H2x2 w2 = *reinterpret_cast<const H2x2*>(t0 + 64 + 2*l);
            float w2a = __low2float(w2.a) + f*__high2float(w2.a);
            float w2b = __low2float(w2.b) + f*__high2float(w2.b);
            float p2a = w2a*se.x, p2b = w2b*se.y;
            av00 = fmaf(p2a, d.y, av00); av10 = fmaf(p2a, d.z, av10); av20 = fmaf(p2a, d.w, av20);
            av01 = fmaf(p2b, d.y, av01); av11 = fmaf(p2b, d.z, av11); av21 = fmaf(p2b, d.w, av21);
        } else {
            __half2 h4 = t0[160 + l];
            float w4 = __low2float(h4) + f*__high2float(h4);
            float ve0 = g_v1[src*96 +      l];
            float ve1 = g_v1[src*96 + 32 + l];
            float ve2 = g_v1[src*96 + 64 + l];
            float dv = ve0*d.y + ve1*d.z + ve2*d.w;
            as2 = fmaf(w4*INV_SQRT3f, dv, as2);
        }
    }
    const float sc = 0.25f;
    *reinterpret_cast<float2*>(&g_as[n*96 + 2*l]) = make_float2(as0*sc, as1*sc);
    if (LAYER == 0){
        int b0 = n*288;
        *reinterpret_cast<float2*>(&g_av[b0 +       2*l]) = make_float2(av00*sc, av01*sc);
        *reinterpret_cast<float2*>(&g_av[b0 +  96 + 2*l]) = make_float2(av10*sc, av11*sc);
        *reinterpret_cast<float2*>(&g_av[b0 + 192 + 2*l]) = make_float2(av20*sc, av21*sc);
    } else {
        g_as[n*96 + 64 + l] = as2*sc;
    }
}

// ---------------- heads ----------------
__global__ void k_head(const float* __restrict__ nodes,
                       const float* __restrict__ Wen1, const float* __restrict__ Wen2,
                       const float* __restrict__ Wmag1, const float* __restrict__ Wmag2,
                       const float* __restrict__ sc_occ, const float* __restrict__ sh_occ,
                       const float* __restrict__ esc, const float* __restrict__ esh,
                       float* __restrict__ out){
    int n = blockIdx.x*8 + threadIdx.y;
    if (n >= Nn) return;
    int t = threadIdx.x;
    const float* s = g_s + n*64;
    float he = 0.f, hm = 0.f;
    #pragma unroll 8
    for (int i = 0; i < 64; i++){
        float si = s[i];
        he = fmaf(si, Wen1[i*32+t], he);
        hm = fmaf(si, Wmag1[i*32+t], hm);
    }
    he *= 0.125f; hm *= 0.125f;
    float pe  = he * Wen2[t];
    float pm0 = hm * Wmag2[t*2+0];
    float pm1 = hm * Wmag2[t*2+1];
    #pragma unroll
    for (int o = 16; o; o >>= 1){
        pe  += __shfl_down_sync(0xffffffffu, pe,  o);
        pm0 += __shfl_down_sync(0xffffffffu, pm0, o);
        pm1 += __shfl_down_sync(0xffffffffu, pm1, o);
    }
    if (t == 0){
        g_atomic[n] = esc[0] * (pe * 0.17677669529f) + esh[0];
        float a0 = nodes[n*4+0], a1 = nodes[n*4+1], a2 = nodes[n*4+2];
        float s0 = a0*sc_occ[0] + a1*sc_occ[2] + a2*sc_occ[4];
        float s1m= a0*sc_occ[1] + a1*sc_occ[3] + a2*sc_occ[5];
        float t0 = a0*sh_occ[0] + a1*sh_occ[2] + a2*sh_occ[4];
        float t1 = a0*sh_occ[1] + a1*sh_occ[3] + a2*sh_occ[5];
        out[Gg + n*2 + 0] = s0 *(pm0 * 0.17677669529f) + t0;
        out[Gg + n*2 + 1] = s1m*(pm1 * 0.17677669529f) + t1;
    }
}

__global__ void k_energy(const int* __restrict__ n_node, float* __restrict__ out){
    __shared__ float sm[256];
    int g = blockIdx.x, t = threadIdx.x;
    int start = 0;
    for (int q = 0; q < g; q++) start += n_node[q];
    int end = start + n_node[g];
    if (start > Nn) start = Nn;
    if (end > Nn) end = Nn;
    float acc = 0.f;
    for (int i = start + t; i < end; i += 256) acc += g_atomic[i];
    sm[t] = acc; __syncthreads();
    #pragma unroll
    for (int o = 128; o; o >>= 1){ if (t < o) sm[t] += sm[t+o]; __syncthreads(); }
    if (t == 0) out[g] = sm[0];
}

// ---------------- launch ----------------
extern "C" void kernel_launch(void* const* d_in, const int* in_sizes, int n_in,
                              void* d_out, int out_size){
    const float* nodes   = (const float*)d_in[0];
    const float* dR      = (const float*)d_in[1];
    const int*   senders = (const int*)  d_in[2];
    const int*   recv    = (const int*)  d_in[3];
    const int*   n_node  = (const int*)  d_in[4];
    const float* W_embed = (const float*)d_in[5];
    const float* W_sc_s  = (const float*)d_in[6];
    const float* W_l1_s  = (const float*)d_in[8];
    const float* W_l1_v  = (const float*)d_in[9];
    const float* Wr0     = (const float*)d_in[10];
    const float* Wr1     = (const float*)d_in[11];
    const float* Wr2     = (const float*)d_in[12];
    const float* W_l2_s  = (const float*)d_in[13];
    const float* W_l2_v  = (const float*)d_in[14];
    const float* W_en1   = (const float*)d_in[15];
    const float* W_en2   = (const float*)d_in[16];
    const float* W_mag1  = (const float*)d_in[17];
    const float* W_mag2  = (const float*)d_in[18];
    const float* sc_occ  = (const float*)d_in[19];
    const float* sh_occ  = (const float*)d_in[20];
    const float* esc     = (const float*)d_in[21];
    const float* esh     = (const float*)d_in[22];
    float* out = (float*)d_out;

    static cudaStream_t sA = nullptr, sB = nullptr;
    static cudaEvent_t evF = nullptr, evA = nullptr, evB = nullptr;
    if (sA == nullptr){
        cudaStreamCreateWithFlags(&sA, cudaStreamNonBlocking);
        cudaStreamCreateWithFlags(&sB, cudaStreamNonBlocking);
        cudaEventCreateWithFlags(&evF, cudaEventDisableTiming);
        cudaEventCreateWithFlags(&evA, cudaEventDisableTiming);
        cudaEventCreateWithFlags(&evB, cudaEventDisableTiming);
    }

    // fork
    cudaEventRecord(evF, 0);
    cudaStreamWaitEvent(sA, evF, 0);
    cudaStreamWaitEvent(sB, evF, 0);

    // stream 0: CSR chain + sort/records
    k_zero_init<<<(Nn + 255)/256, 256>>>();
    k_count<<<(Ee + 255)/256, 256>>>(recv);
    k_scan<<<1, 1024>>>();
    k_scatter<<<(Ee + 255)/256, 256>>>(recv);
    k_sortrec<<<SORT_NB, 256>>>(dR, senders);

    // stream A: embed -> phase A layer 0
    k_embed<<<(Nn*64 + 255)/256, 256, 0, sA>>>(nodes, W_embed);
    k_phA0<<<2*NBs, 256, 0, sA>>>(nodes, W_sc_s, W_l1_s);

    // stream B: radial table -> half2 pack
    k_table<<<TAB_NB, 256, 0, sB>>>(Wr0, Wr1, Wr2);
    k_pack<<<(2*TAB*192 + 255)/256, 256, 0, sB>>>();

    // join
    cudaEventRecord(evA, sA);
    cudaEventRecord(evB, sB);
    cudaStreamWaitEvent(0, evA, 0);
    cudaStreamWaitEvent(0, evB, 0);

    // layer 0 tail
    k_gather<0><<<(Nn + 7)/8, dim3(32, 8)>>>();
    k_phB0<<<NBs + NBv, 256>>>(W_l2_s, W_l2_v);
    // layer 1
    k_phA1<<<2*NBs + NBv, 256>>>(nodes, W_sc_s + 24576, W_l1_s + 4096, W_l1_v + 1024);
    k_gather<1><<<(Nn + 7)/8, dim3(32, 8)>>>();
    k_phB1<<<NBs, 256>>>(W_l2_s + 9216);

    k_head<<<(Nn + 7)/8, dim3(32, 8)>>>(nodes, W_en1, W_en2, W_mag1, W_mag2,
                                        sc_occ, sh_occ, esc, esh, out);
    k_energy<<<Gg, 256>>>(n_node, out);
}

// round 15
// speedup vs baseline: 1.3214x; 1.1013x over previous
#include <cuda_runtime.h>
#include <cuda_fp16.h>
#include <math.h>

#define Nn   20000
#define Ee   320000
#define Gg   16
#define TAB  8192
#define RMAXf 4.0f
#define RINf  3.5f
#define PI_F  3.14159265358979f
#define SQRT3f 1.7320508075688772f
#define INV_SQRT3f 0.5773502691896258f

#define NB64s 313   // (Nn+63)/64
#define NB64v 938   // (3*Nn+63)/64

// ---------------- device scratch ----------------
__device__ __align__(16) float g_s  [Nn*64];
__device__ __align__(16) float g_v  [Nn*96];     // raw o_v, rows (n*3+c) x 32
__device__ __align__(16) float g_s1 [Nn*64];
__device__ __align__(16) float g_v1 [Nn*96];
__device__ __align__(16) float g_scs[Nn*96];
__device__ __align__(16) float g_as [Nn*96];
__device__ __align__(16) float g_av [Nn*288];
__device__ __align__(16) float g_gate[Nn*32];
__device__ __align__(16) float g_tab [2*(TAB+1)*192];
__device__ __align__(16) __half2 g_tabh[2*TAB*192];
__device__ __align__(16) float4 g_edir[Ee];      // {x, shx, shy, shz}
__device__ int   g_esrc[Ee];
__device__ float g_atomic[Nn];
__device__ int   g_cnt[Nn];
__device__ int   g_off[Nn+1];
__device__ int   g_cur[Nn];
__device__ int   g_elist[Ee];

struct __align__(8) H2x2 { __half2 a, b; };

__device__ __forceinline__ float silu_f(float x){ return x / (1.0f + expf(-x)); }

__device__ __forceinline__ unsigned long long packdup(float a){
    unsigned long long r;
    asm("mov.b64 %0, {%1, %1};" : "=l"(r) : "f"(a));
    return r;
}
__device__ __forceinline__ void unpack2(unsigned long long v, float& lo, float& hi){
    asm("mov.b64 {%0, %1}, %2;" : "=f"(lo), "=f"(hi) : "l"(v));
}
__device__ __forceinline__ void fma2(unsigned long long& d, unsigned long long a, unsigned long long b){
    asm("fma.rn.f32x2 %0, %1, %2, %0;" : "+l"(d) : "l"(a), "l"(b));
}

// ---------------- CSR ----------------
__global__ void k_zero_init(){
    int i = blockIdx.x*256 + threadIdx.x;
    if (i < Nn) g_cnt[i] = 0;
}

__global__ void k_count(const int* __restrict__ recv){
    int e = blockIdx.x*256 + threadIdx.x;
    if (e < Ee) atomicAdd(&g_cnt[recv[e]], 1);
}

__global__ void k_scan(){
    const int PER = 20;
    int t = threadIdx.x;
    int base = t * PER;
    int loc[PER]; int s = 0;
    #pragma unroll
    for (int i = 0; i < PER; i++){
        int idx = base + i;
        int x = (idx < Nn) ? g_cnt[idx] : 0;
        loc[i] = s; s += x;
    }
    int lane = t & 31, wid = t >> 5;
    int v = s;
    #pragma unroll
    for (int o = 1; o < 32; o <<= 1){
        int y = __shfl_up_sync(0xffffffffu, v, o);
        if (lane >= o) v += y;
    }
    __shared__ int wsum[32];
    if (lane == 31) wsum[wid] = v;
    __syncthreads();
    if (wid == 0){
        int w = wsum[lane];
        #pragma unroll
        for (int o = 1; o < 32; o <<= 1){
            int y = __shfl_up_sync(0xffffffffu, w, o);
            if (lane >= o) w += y;
        }
        wsum[lane] = w;
    }
    __syncthreads();
    int excl = v - s + (wid ? wsum[wid-1] : 0);
    #pragma unroll
    for (int i = 0; i < PER; i++){
        int idx = base + i;
        int off = excl + loc[i];
        if (idx < Nn){ g_off[idx] = off; g_cur[idx] = off; }
        else if (idx == Nn) g_off[Nn] = off;
    }
}

__global__ void k_scatter(const int* __restrict__ recv){
    int e = blockIdx.x*256 + threadIdx.x;
    if (e < Ee){
        int p = atomicAdd(&g_cur[recv[e]], 1);
        g_elist[p] = e;
    }
}

// ---------------- sort (L1-resident global) + cooperative edge records ----------------
#define SORT_NB  79          // (Nn+255)/256

__global__ void k_sortrec(const float* __restrict__ dR, const int* __restrict__ senders){
    int blk = blockIdx.x, tid = threadIdx.x;
    int n = blk*256 + tid;
    if (n < Nn){
        int b = g_off[n], e2 = g_off[n+1];
        for (int i = b+1; i < e2; i++){
            int key = g_elist[i];
            int j = i-1;
            while (j >= b && g_elist[j] > key){ g_elist[j+1] = g_elist[j]; j--; }
            g_elist[j+1] = key;
        }
    }
    __syncthreads();
    int n0 = blk*256;
    int n1 = n0 + 256; if (n1 > Nn) n1 = Nn;
    int p0 = g_off[n0], p1 = g_off[n1];
    for (int p = p0 + tid; p < p1; p += 256){
        int e = g_elist[p];
        float dx = dR[3*e+0], dy = dR[3*e+1], dz = dR[3*e+2];
        float r = sqrtf(dx*dx + dy*dy + dz*dz);
        float inv = 1.0f / fmaxf(r, 1e-6f);
        float x = fminf(r * ((float)TAB / RMAXf), (float)TAB);
        g_edir[p] = make_float4(x, SQRT3f*dx*inv, SQRT3f*dy*inv, SQRT3f*dz*inv);
        g_esrc[p] = senders[e];
    }
}

// ---------------- embedding ----------------
__global__ void k_embed(const float* __restrict__ nodes, const float* __restrict__ Wemb){
    int idx = blockIdx.x*256 + threadIdx.x;
    if (idx >= Nn*64) return;
    int n = idx >> 6, o = idx & 63;
    float acc = 0.f;
    #pragma unroll
    for (int e = 0; e < 4; e++) acc = fmaf(nodes[n*4+e], Wemb[e*64+o], acc);
    g_s[idx] = acc * 0.5f;
}

// ---------------- radial table ----------------
#define TROWS    (2*(TAB+1))
#define TAB_NB   ((TROWS+3)/4)

__global__ void k_table(const float* __restrict__ Wr0, const float* __restrict__ Wr1,
                        const float* __restrict__ Wr2){
    __shared__ float h1s[4][64];
    __shared__ float h2s[4][64];
    int tid = threadIdx.x;
    int q = blockIdx.x*4 + (tid >> 6);
    int t = tid & 63, sub = tid >> 6;
    bool act = (q < TROWS);
    int l = act ? q / (TAB+1) : 0;
    int row = act ? q % (TAB+1) : 0;
    const float* R0 = Wr0 + l*512;
    const float* R1 = Wr1 + l*4096;
    const float* R2 = Wr2 + l*12288;
    float r = (float)row * (RMAXf / (float)TAB);
    float rs = fmaxf(r, 1e-6f);
    float env;
    if (r < RINf) env = 1.0f;
    else if (r > RMAXf) env = 0.0f;
    else { float tt = (r - RINf) / (RMAXf - RINf); env = 0.5f*(cosf(PI_F*tt)+1.0f); }
    float remb[8];
    #pragma unroll
    for (int nb = 1; nb <= 8; nb++)
        remb[nb-1] = 0.70710678f * sinf((float)nb * PI_F * rs / RMAXf) / rs * env;
    float h = 0.f;
    #pragma unroll
    for (int k = 0; k < 8; k++) h = fmaf(remb[k], R0[k*64+t], h);
    h1s[sub][t] = silu_f(h * 0.35355339f);
    __syncthreads();
    float h2 = 0.f;
    #pragma unroll
    for (int k = 0; k < 64; k++) h2 = fmaf(h1s[sub][k], R1[k*64+t], h2);
    h2s[sub][t] = silu_f(h2 * 0.125f);
    __syncthreads();
    if (act){
        #pragma unroll
        for (int j = 0; j < 3; j++){
            int o = t + 64*j;
            float w = 0.f;
            #pragma unroll 8
            for (int k = 0; k < 64; k++) w = fmaf(h2s[sub][k], R2[k*192+o], w);
            g_tab[q*192 + o] = w * 0.125f;
        }
    }
}

__global__ void k_pack(){
    int idx = blockIdx.x*256 + threadIdx.x;
    if (idx >= 2*TAB*192) return;
    int l   = idx / (TAB*192);
    int rem = idx % (TAB*192);
    int row = rem / 192, o = rem % 192;
    float v0 = g_tab[(l*(TAB+1) + row    )*192 + o];
    float v1 = g_tab[(l*(TAB+1) + row + 1)*192 + o];
    g_tabh[idx] = __floats2half2_rn(v0, v1 - v0);
}

// ---------------- gemm body (f32x2, 32-wide k-chunks, TM=4 rows/thread, 64-row tiles) ----------------
#define AS_STRIDE 68
template<int K, int NC, int MODE, int ASTRIDE>
__device__ __forceinline__ void gemm_body(float* sm,
            const float* __restrict__ A, const float* __restrict__ B,
            const float* __restrict__ D, float* __restrict__ C,
            const float* __restrict__ attrs, int M, float alpha, int blk){
    constexpr int TN = NC / 16;
    constexpr int TH = TN / 2;
    float* As = sm;                    // [32][AS_STRIDE]
    float* Bs = sm + 32*AS_STRIDE;     // [32][NC]
    int tid = threadIdx.x;
    int mg = tid & 15, ng = tid >> 4;
    int m0 = blk * 64;
    unsigned long long acc2[4][TH];
    #pragma unroll
    for (int i = 0; i < 4; i++)
        #pragma unroll
        for (int j = 0; j < TH; j++) acc2[i][j] = 0ull;

    for (int kc = 0; kc < K; kc += 32){
        #pragma unroll
        for (int q = 0; q < 8; q++){
            int e2 = q*256 + tid;
            int r = e2 >> 5, c = e2 & 31;
            int row = m0 + r;
            float val = 0.f;
            if (row < M){
                int k = kc + c;
                if (MODE == 1)      val = A[row*64 + (k>>2)] * attrs[row*4 + (k&3)];
                else if (MODE == 5) val = A[row*32 + k] * attrs[(row/3)*32 + k];
                else                val = A[row*ASTRIDE + k];
            }
            As[c*AS_STRIDE + r] = val;
        }
        for (int e2 = tid; e2 < 32*NC; e2 += 256){
            int r = e2 / NC, c = e2 % NC;
            Bs[r*NC + c] = B[(kc+r)*NC + c];
        }
        __syncthreads();
        #pragma unroll
        for (int kk = 0; kk < 32; kk++){
            float4 a0 = *(const float4*)(As + kk*AS_STRIDE + mg*4);
            float aa[4] = {a0.x, a0.y, a0.z, a0.w};
            unsigned long long aa2[4];
            #pragma unroll
            for (int i = 0; i < 4; i++) aa2[i] = packdup(aa[i]);
            const unsigned long long* bp =
                (const unsigned long long*)(Bs + kk*NC + ng*TN);
            unsigned long long bb2[TH];
            #pragma unroll
            for (int j = 0; j < TH; j++) bb2[j] = bp[j];
            #pragma unroll
            for (int i = 0; i < 4; i++)
                #pragma unroll
                for (int j = 0; j < TH; j++) fma2(acc2[i][j], aa2[i], bb2[j]);
        }
        __syncthreads();
    }
    #pragma unroll
    for (int i = 0; i < 4; i++){
        int row = m0 + mg*4 + i;
        if (row >= M) continue;
        #pragma unroll
        for (int j = 0; j < TH; j++){
            float vlo, vhi;
            unpack2(acc2[i][j], vlo, vhi);
            int col = ng*TN + 2*j;
            float val0 = vlo * alpha;
            float val1 = vhi * alpha;
            if (MODE == 2){
                val0 += D[row*96 + col];
                val1 += D[row*96 + col + 1];
                float sv0 = silu_f(val0);
                float sv1 = silu_f(val1);
                if (col < 64){
                    g_s[row*64 + col]   = sv0;
                    g_s[row*64 + col+1] = sv1;
                } else {
                    g_gate[row*32 + (col-64)]   = sv0;
                    g_gate[row*32 + (col-64)+1] = sv1;
                }
            } else {
                C[row*NC + col]   = val0;
                C[row*NC + col+1] = val1;
            }
        }
    }
}

#define A_SCS 0.0625f
#define A_S1  0.125f
#define A_V1  0.17677669529f
#define A_O   0.10206207262f

#define SM_FLOATS (32*AS_STRIDE + 32*96)

// phase A, layer 0: sc_s | l1_s
__global__ __launch_bounds__(256, 3)
void k_phA0(const float* __restrict__ nodes, const float* __restrict__ WscS,
            const float* __restrict__ Wl1s){
    __shared__ __align__(16) float sm[SM_FLOATS];
    int b = blockIdx.x;
    if (b < NB64s) gemm_body<256,96,1,256>(sm, g_s, WscS, nullptr, g_scs, nodes, Nn, A_SCS, b);
    else           gemm_body< 64,64,0, 64>(sm, g_s, Wl1s, nullptr, g_s1, nullptr, Nn, A_S1, b-NB64s);
}

// phase A, layer 1: sc_s | l1_s | gated l1_v
__global__ __launch_bounds__(256, 3)
void k_phA1(const float* __restrict__ nodes, const float* __restrict__ WscS,
            const float* __restrict__ Wl1s, const float* __restrict__ Wl1v){
    __shared__ __align__(16) float sm[SM_FLOATS];
    int b = blockIdx.x;
    if (b < NB64s)        gemm_body<256,96,1,256>(sm, g_s, WscS, nullptr, g_scs, nodes, Nn, A_SCS, b);
    else if (b < 2*NB64s) gemm_body< 64,64,0, 64>(sm, g_s, Wl1s, nullptr, g_s1, nullptr, Nn, A_S1, b-NB64s);
    else                  gemm_body< 32,32,5, 32>(sm, g_v, Wl1v, nullptr, g_v1, g_gate, 3*Nn, A_V1, b-2*NB64s);
}

// phase B, layer 0: l2_s (K=64 effective) | l2_v (K=64 effective)
__global__ __launch_bounds__(256, 3)
void k_phB0(const float* __restrict__ Wl2s, const float* __restrict__ Wl2v){
    __shared__ __align__(16) float sm[SM_FLOATS];
    int b = blockIdx.x;
    if (b < NB64s) gemm_body<64,96,2,96>(sm, g_as, Wl2s, g_scs, nullptr, nullptr, Nn, A_O, b);
    else           gemm_body<64,32,0,96>(sm, g_av, Wl2v, nullptr, g_v, nullptr, 3*Nn, A_O, b-NB64s);
}

// phase B, layer 1: l2_s only (full K=96)
__global__ __launch_bounds__(256, 3)
void k_phB1(const float* __restrict__ Wl2s){
    __shared__ __align__(16) float sm[SM_FLOATS];
    gemm_body<96,96,2,96>(sm, g_as, Wl2s, g_scs, nullptr, nullptr, Nn, A_O, blockIdx.x);
}

// ---------------- gather (lane l owns features 2l, 2l+1) ----------------
template<int LAYER>
__global__ void k_gather(){
    int n = blockIdx.x*8 + threadIdx.y;
    if (n >= Nn) return;
    int l = threadIdx.x;
    const __half2* tb_base = g_tabh + LAYER*(TAB*192);
    int beg = g_off[n], end = g_off[n+1];
    float as0 = 0.f, as1 = 0.f, as2 = 0.f;
    float av00=0,av01=0, av10=0,av11=0, av20=0,av21=0;
    #pragma unroll 4
    for (int p = beg; p < end; p++){
        float4 d = g_edir[p];
        int src = g_esrc[p];
        int gi = (int)d.x; gi = min(gi, TAB-1);
        float f = d.x - (float)gi;
        const __half2* t0 = tb_base + gi*192;
        H2x2 w1 = *reinterpret_cast<const H2x2*>(t0 + 2*l);
        float w1a = __low2float(w1.a) + f*__high2float(w1.a);
        float w1b = __low2float(w1.b) + f*__high2float(w1.b);
        float2 se = *reinterpret_cast<const float2*>(&g_s1[src*64 + 2*l]);
        as0 = fmaf(w1a, se.x, as0);
        as1 = fmaf(w1b, se.y, as1);
        if (LAYER == 0){
            H2x2 w2 = *reinterpret_cast<const H2x2*>(t0 + 64 + 2*l);
            float w2a = __low2float(w2.a) + f*__high2float(w2.a);
            float w2b = __low2float(w2.b) + f*__high2float(w2.b);
            float p2a = w2a*se.x, p2b = w2b*se.y;
            av00 = fmaf(p2a, d.y, av00); av10 = fmaf(p2a, d.z, av10); av20 = fmaf(p2a, d.w, av20);
            av01 = fmaf(p2b, d.y, av01); av11 = fmaf(p2b, d.z, av11); av21 = fmaf(p2b, d.w, av21);
        } else {
            __half2 h4 = t0[160 + l];
            float w4 = __low2float(h4) + f*__high2float(h4);
            float ve0 = g_v1[src*96 +      l];
            float ve1 = g_v1[src*96 + 32 + l];
            float ve2 = g_v1[src*96 + 64 + l];
            float dv = ve0*d.y + ve1*d.z + ve2*d.w;
            as2 = fmaf(w4*INV_SQRT3f, dv, as2);
        }
    }
    const float sc = 0.25f;
    *reinterpret_cast<float2*>(&g_as[n*96 + 2*l]) = make_float2(as0*sc, as1*sc);
    if (LAYER == 0){
        int b0 = n*288;
        *reinterpret_cast<float2*>(&g_av[b0 +       2*l]) = make_float2(av00*sc, av01*sc);
        *reinterpret_cast<float2*>(&g_av[b0 +  96 + 2*l]) = make_float2(av10*sc, av11*sc);
        *reinterpret_cast<float2*>(&g_av[b0 + 192 + 2*l]) = make_float2(av20*sc, av21*sc);
    } else {
        g_as[n*96 + 64 + l] = as2*sc;
    }
}

// ---------------- heads ----------------
__global__ void k_head(const float* __restrict__ nodes,
                       const float* __restrict__ Wen1, const float* __restrict__ Wen2,
                       const float* __restrict__ Wmag1, const float* __restrict__ Wmag2,
                       const float* __restrict__ sc_occ, const float* __restrict__ sh_occ,
                       const float* __restrict__ esc, const float* __restrict__ esh,
                       float* __restrict__ out){
    int n = blockIdx.x*8 + threadIdx.y;
    if (n >= Nn) return;
    int t = threadIdx.x;
    const float* s = g_s + n*64;
    float he = 0.f, hm = 0.f;
    #pragma unroll 8
    for (int i = 0; i < 64; i++){
        float si = s[i];
        he = fmaf(si, Wen1[i*32+t], he);
        hm = fmaf(si, Wmag1[i*32+t], hm);
    }
    he *= 0.125f; hm *= 0.125f;
    float pe  = he * Wen2[t];
    float pm0 = hm * Wmag2[t*2+0];
    float pm1 = hm * Wmag2[t*2+1];
    #pragma unroll
    for (int o = 16; o; o >>= 1){
        pe  += __shfl_down_sync(0xffffffffu, pe,  o);
        pm0 += __shfl_down_sync(0xffffffffu, pm0, o);
        pm1 += __shfl_down_sync(0xffffffffu, pm1, o);
    }
    if (t == 0){
        g_atomic[n] = esc[0] * (pe * 0.17677669529f) + esh[0];
        float a0 = nodes[n*4+0], a1 = nodes[n*4+1], a2 = nodes[n*4+2];
        float s0 = a0*sc_occ[0] + a1*sc_occ[2] + a2*sc_occ[4];
        float s1m= a0*sc_occ[1] + a1*sc_occ[3] + a2*sc_occ[5];
        float t0 = a0*sh_occ[0] + a1*sh_occ[2] + a2*sh_occ[4];
        float t1 = a0*sh_occ[1] + a1*sh_occ[3] + a2*sh_occ[5];
        out[Gg + n*2 + 0] = s0 *(pm0 * 0.17677669529f) + t0;
        out[Gg + n*2 + 1] = s1m*(pm1 * 0.17677669529f) + t1;
    }
}

__global__ void k_energy(const int* __restrict__ n_node, float* __restrict__ out){
    __shared__ float sm[256];
    int g = blockIdx.x, t = threadIdx.x;
    int start = 0;
    for (int q = 0; q < g; q++) start += n_node[q];
    int end = start + n_node[g];
    if (start > Nn) start = Nn;
    if (end > Nn) end = Nn;
    float acc = 0.f;
    for (int i = start + t; i < end; i += 256) acc += g_atomic[i];
    sm[t] = acc; __syncthreads();
    #pragma unroll
    for (int o = 128; o; o >>= 1){ if (t < o) sm[t] += sm[t+o]; __syncthreads(); }
    if (t == 0) out[g] = sm[0];
}

// ---------------- launch ----------------
extern "C" void kernel_launch(void* const* d_in, const int* in_sizes, int n_in,
                              void* d_out, int out_size){
    const float* nodes   = (const float*)d_in[0];
    const float* dR      = (const float*)d_in[1];
    const int*   senders = (const int*)  d_in[2];
    const int*   recv    = (const int*)  d_in[3];
    const int*   n_node  = (const int*)  d_in[4];
    const float* W_embed = (const float*)d_in[5];
    const float* W_sc_s  = (const float*)d_in[6];
    const float* W_l1_s  = (const float*)d_in[8];
    const float* W_l1_v  = (const float*)d_in[9];
    const float* Wr0     = (const float*)d_in[10];
    const float* Wr1     = (const float*)d_in[11];
    const float* Wr2     = (const float*)d_in[12];
    const float* W_l2_s  = (const float*)d_in[13];
    const float* W_l2_v  = (const float*)d_in[14];
    const float* W_en1   = (const float*)d_in[15];
    const float* W_en2   = (const float*)d_in[16];
    const float* W_mag1  = (const float*)d_in[17];
    const float* W_mag2  = (const float*)d_in[18];
    const float* sc_occ  = (const float*)d_in[19];
    const float* sh_occ  = (const float*)d_in[20];
    const float* esc     = (const float*)d_in[21];
    const float* esh     = (const float*)d_in[22];
    float* out = (float*)d_out;

    static cudaStream_t sA = nullptr, sB = nullptr;
    static cudaEvent_t evF = nullptr, evA = nullptr, evB = nullptr;
    if (sA == nullptr){
        cudaStreamCreateWithFlags(&sA, cudaStreamNonBlocking);
        cudaStreamCreateWithFlags(&sB, cudaStreamNonBlocking);
        cudaEventCreateWithFlags(&evF, cudaEventDisableTiming);
        cudaEventCreateWithFlags(&evA, cudaEventDisableTiming);
        cudaEventCreateWithFlags(&evB, cudaEventDisableTiming);
    }

    // fork
    cudaEventRecord(evF, 0);
    cudaStreamWaitEvent(sA, evF, 0);
    cudaStreamWaitEvent(sB, evF, 0);

    // stream 0: CSR chain + sort/records
    k_zero_init<<<(Nn + 255)/256, 256>>>();
    k_count<<<(Ee + 255)/256, 256>>>(recv);
    k_scan<<<1, 1024>>>();
    k_scatter<<<(Ee + 255)/256, 256>>>(recv);
    k_sortrec<<<SORT_NB, 256>>>(dR, senders);

    // stream A: embed -> phase A layer 0
    k_embed<<<(Nn*64 + 255)/256, 256, 0, sA>>>(nodes, W_embed);
    k_phA0<<<2*NB64s, 256, 0, sA>>>(nodes, W_sc_s, W_l1_s);

    // stream B: radial table -> half2 pack
    k_table<<<TAB_NB, 256, 0, sB>>>(Wr0, Wr1, Wr2);
    k_pack<<<(2*TAB*192 + 255)/256, 256, 0, sB>>>();

    // join
    cudaEventRecord(evA, sA);
    cudaEventRecord(evB, sB);
    cudaStreamWaitEvent(0, evA, 0);
    cudaStreamWaitEvent(0, evB, 0);

    // layer 0 tail
    k_gather<0><<<(Nn + 7)/8, dim3(32, 8)>>>();
    k_phB0<<<NB64s + NB64v, 256>>>(W_l2_s, W_l2_v);
    // layer 1
    k_phA1<<<2*NB64s + NB64v, 256>>>(nodes, W_sc_s + 24576, W_l1_s + 4096, W_l1_v + 1024);
    k_gather<1><<<(Nn + 7)/8, dim3(32, 8)>>>();
    k_phB1<<<NB64s, 256>>>(W_l2_s + 9216);

    k_head<<<(Nn + 7)/8, dim3(32, 8)>>>(nodes, W_en1, W_en2, W_mag1, W_mag2,
                                        sc_occ, sh_occ, esc, esh, out);
    k_energy<<<Gg, 256>>>(n_node, out);
}

// round 17
// speedup vs baseline: 1.3874x; 1.0500x over previous
#include <cuda_runtime.h>
#include <cuda_fp16.h>
#include <math.h>

#define Nn   20000
#define Ee   320000
#define Gg   16
#define TAB  8192
#define RMAXf 4.0f
#define RINf  3.5f
#define PI_F  3.14159265358979f
#define SQRT3f 1.7320508075688772f
#define INV_SQRT3f 0.5773502691896258f

#define NB64s 313   // (Nn+63)/64
#define NB64v 938   // (3*Nn+63)/64

// ---------------- device scratch ----------------
__device__ __align__(16) float g_s  [Nn*64];
__device__ __align__(16) float g_v  [Nn*96];     // raw o_v, rows (n*3+c) x 32
__device__ __align__(16) float g_s1 [Nn*64];
__device__ __align__(16) float g_v1 [Nn*96];
__device__ __align__(16) float g_scs[Nn*96];
__device__ __align__(16) float g_as [Nn*96];
__device__ __align__(16) float g_av [Nn*288];
__device__ __align__(16) float g_gate[Nn*32];
__device__ __align__(16) float g_tab [2*(TAB+1)*192];
__device__ __align__(16) __half2 g_tabh[2*TAB*192];
__device__ __align__(16) float4 g_edir[Ee];      // {x, shx, shy, shz}
__device__ int   g_esrc[Ee];
__device__ float g_atomic[Nn];
__device__ int   g_cnt[Nn];
__device__ int   g_off[Nn+1];
__device__ int   g_cur[Nn];
__device__ int   g_elist[Ee];

struct __align__(8) H2x2 { __half2 a, b; };

__device__ __forceinline__ float silu_f(float x){ return x / (1.0f + expf(-x)); }

__device__ __forceinline__ unsigned long long packdup(float a){
    unsigned long long r;
    asm("mov.b64 %0, {%1, %1};" : "=l"(r) : "f"(a));
    return r;
}
__device__ __forceinline__ void unpack2(unsigned long long v, float& lo, float& hi){
    asm("mov.b64 {%0, %1}, %2;" : "=f"(lo), "=f"(hi) : "l"(v));
}
__device__ __forceinline__ void fma2(unsigned long long& d, unsigned long long a, unsigned long long b){
    asm("fma.rn.f32x2 %0, %1, %2, %0;" : "+l"(d) : "l"(a), "l"(b));
}

// ---------------- CSR ----------------
__global__ void k_zero_init(){
    int i = blockIdx.x*256 + threadIdx.x;
    if (i < Nn) g_cnt[i] = 0;
}

__global__ void k_count(const int* __restrict__ recv){
    int e = blockIdx.x*256 + threadIdx.x;
    if (e < Ee) atomicAdd(&g_cnt[recv[e]], 1);
}

__global__ void k_scan(){
    const int PER = 20;
    int t = threadIdx.x;
    int base = t * PER;
    int loc[PER]; int s = 0;
    #pragma unroll
    for (int i = 0; i < PER; i++){
        int idx = base + i;
        int x = (idx < Nn) ? g_cnt[idx] : 0;
        loc[i] = s; s += x;
    }
    int lane = t & 31, wid = t >> 5;
    int v = s;
    #pragma unroll
    for (int o = 1; o < 32; o <<= 1){
        int y = __shfl_up_sync(0xffffffffu, v, o);
        if (lane >= o) v += y;
    }
    __shared__ int wsum[32];
    if (lane == 31) wsum[wid] = v;
    __syncthreads();
    if (wid == 0){
        int w = wsum[lane];
        #pragma unroll
        for (int o = 1; o < 32; o <<= 1){
            int y = __shfl_up_sync(0xffffffffu, w, o);
            if (lane >= o) w += y;
        }
        wsum[lane] = w;
    }
    __syncthreads();
    int excl = v - s + (wid ? wsum[wid-1] : 0);
    #pragma unroll
    for (int i = 0; i < PER; i++){
        int idx = base + i;
        int off = excl + loc[i];
        if (idx < Nn){ g_off[idx] = off; g_cur[idx] = off; }
        else if (idx == Nn) g_off[Nn] = off;
    }
}

__global__ void k_scatter(const int* __restrict__ recv){
    int e = blockIdx.x*256 + threadIdx.x;
    if (e < Ee){
        int p = atomicAdd(&g_cur[recv[e]], 1);
        g_elist[p] = e;
    }
}

// ---------------- sort (register bitonic) + cooperative edge records ----------------
#define SORT_NB  79          // (Nn+255)/256

__global__ void k_sortrec(const float* __restrict__ dR, const int* __restrict__ senders){
    int blk = blockIdx.x, tid = threadIdx.x;
    int n = blk*256 + tid;
    if (n < Nn){
        int b = g_off[n], e2 = g_off[n+1];
        int cnt = e2 - b;
        if (cnt <= 32){
            int buf[32];
            #pragma unroll
            for (int i = 0; i < 32; i++)
                buf[i] = (i < cnt) ? g_elist[b+i] : 0x7fffffff;
            // bitonic sorting network, fully unrolled, register-resident
            #pragma unroll
            for (int kk = 2; kk <= 32; kk <<= 1){
                #pragma unroll
                for (int j = kk >> 1; j > 0; j >>= 1){
                    #pragma unroll
                    for (int i = 0; i < 32; i++){
                        int ixj = i ^ j;
                        if (ixj > i){
                            bool up = ((i & kk) == 0);
                            int x = buf[i], y = buf[ixj];
                            bool sw = up ? (x > y) : (x < y);
                            if (sw){ buf[i] = y; buf[ixj] = x; }
                        }
                    }
                }
            }
            #pragma unroll
            for (int i = 0; i < 32; i++)
                if (i < cnt) g_elist[b+i] = buf[i];
        } else {
            // rare fallback (deg > 32): global insertion sort
            for (int i = b+1; i < e2; i++){
                int key = g_elist[i];
                int j = i-1;
                while (j >= b && g_elist[j] > key){ g_elist[j+1] = g_elist[j]; j--; }
                g_elist[j+1] = key;
            }
        }
    }
    __syncthreads();
    int n0 = blk*256;
    int n1 = n0 + 256; if (n1 > Nn) n1 = Nn;
    int p0 = g_off[n0], p1 = g_off[n1];
    for (int p = p0 + tid; p < p1; p += 256){
        int e = g_elist[p];
        float dx = dR[3*e+0], dy = dR[3*e+1], dz = dR[3*e+2];
        float r = sqrtf(dx*dx + dy*dy + dz*dz);
        float inv = 1.0f / fmaxf(r, 1e-6f);
        float x = fminf(r * ((float)TAB / RMAXf), (float)TAB);
        g_edir[p] = make_float4(x, SQRT3f*dx*inv, SQRT3f*dy*inv, SQRT3f*dz*inv);
        g_esrc[p] = senders[e];
    }
}

// ---------------- embedding ----------------
__global__ void k_embed(const float* __restrict__ nodes, const float* __restrict__ Wemb){
    int idx = blockIdx.x*256 + threadIdx.x;
    if (idx >= Nn*64) return;
    int n = idx >> 6, o = idx & 63;
    float acc = 0.f;
    #pragma unroll
    for (int e = 0; e < 4; e++) acc = fmaf(nodes[n*4+e], Wemb[e*64+o], acc);
    g_s[idx] = acc * 0.5f;
}

// ---------------- radial table ----------------
#define TROWS    (2*(TAB+1))
#define TAB_NB   ((TROWS+3)/4)

__global__ void k_table(const float* __restrict__ Wr0, const float* __restrict__ Wr1,
                        const float* __restrict__ Wr2){
    __shared__ float h1s[4][64];
    __shared__ float h2s[4][64];
    int tid = threadIdx.x;
    int q = blockIdx.x*4 + (tid >> 6);
    int t = tid & 63, sub = tid >> 6;
    bool act = (q < TROWS);
    int l = act ? q / (TAB+1) : 0;
    int row = act ? q % (TAB+1) : 0;
    const float* R0 = Wr0 + l*512;
    const float* R1 = Wr1 + l*4096;
    const float* R2 = Wr2 + l*12288;
    float r = (float)row * (RMAXf / (float)TAB);
    float rs = fmaxf(r, 1e-6f);
    float env;
    if (r < RINf) env = 1.0f;
    else if (r > RMAXf) env = 0.0f;
    else { float tt = (r - RINf) / (RMAXf - RINf); env = 0.5f*(cosf(PI_F*tt)+1.0f); }
    float remb[8];
    #pragma unroll
    for (int nb = 1; nb <= 8; nb++)
        remb[nb-1] = 0.70710678f * sinf((float)nb * PI_F * rs / RMAXf) / rs * env;
    float h = 0.f;
    #pragma unroll
    for (int k = 0; k < 8; k++) h = fmaf(remb[k], R0[k*64+t], h);
    h1s[sub][t] = silu_f(h * 0.35355339f);
    __syncthreads();
    float h2 = 0.f;
    #pragma unroll
    for (int k = 0; k < 64; k++) h2 = fmaf(h1s[sub][k], R1[k*64+t], h2);
    h2s[sub][t] = silu_f(h2 * 0.125f);
    __syncthreads();
    if (act){
        #pragma unroll
        for (int j = 0; j < 3; j++){
            int o = t + 64*j;
            float w = 0.f;
            #pragma unroll 8
            for (int k = 0; k < 64; k++) w = fmaf(h2s[sub][k], R2[k*192+o], w);
            g_tab[q*192 + o] = w * 0.125f;
        }
    }
}

__global__ void k_pack(){
    int idx = blockIdx.x*256 + threadIdx.x;
    if (idx >= 2*TAB*192) return;
    int l   = idx / (TAB*192);
    int rem = idx % (TAB*192);
    int row = rem / 192, o = rem % 192;
    float v0 = g_tab[(l*(TAB+1) + row    )*192 + o];
    float v1 = g_tab[(l*(TAB+1) + row + 1)*192 + o];
    g_tabh[idx] = __floats2half2_rn(v0, v1 - v0);
}

// ---------------- gemm body (f32x2, 32-wide k-chunks, TM=4 rows/thread, 64-row tiles) ----------------
#define AS_STRIDE 68
template<int K, int NC, int MODE, int ASTRIDE>
__device__ __forceinline__ void gemm_body(float* sm,
            const float* __restrict__ A, const float* __restrict__ B,
            const float* __restrict__ D, float* __restrict__ C,
            const float* __restrict__ attrs, int M, float alpha, int blk){
    constexpr int TN = NC / 16;
    constexpr int TH = TN / 2;
    float* As = sm;                    // [32][AS_STRIDE]
    float* Bs = sm + 32*AS_STRIDE;     // [32][NC]
    int tid = threadIdx.x;
    int mg = tid & 15, ng = tid >> 4;
    int m0 = blk * 64;
    unsigned long long acc2[4][TH];
    #pragma unroll
    for (int i = 0; i < 4; i++)
        #pragma unroll
        for (int j = 0; j < TH; j++) acc2[i][j] = 0ull;

    for (int kc = 0; kc < K; kc += 32){
        #pragma unroll
        for (int q = 0; q < 8; q++){
            int e2 = q*256 + tid;
            int r = e2 >> 5, c = e2 & 31;
            int row = m0 + r;
            float val = 0.f;
            if (row < M){
                int k = kc + c;
                if (MODE == 1)      val = A[row*64 + (k>>2)] * attrs[row*4 + (k&3)];
                else if (MODE == 5) val = A[row*32 + k] * attrs[(row/3)*32 + k];
                else                val = A[row*ASTRIDE + k];
            }
            As[c*AS_STRIDE + r] = val;
        }
        for (int e2 = tid; e2 < 32*NC; e2 += 256){
            int r = e2 / NC, c = e2 % NC;
            Bs[r*NC + c] = B[(kc+r)*NC + c];
        }
        __syncthreads();
        #pragma unroll
        for (int kk = 0; kk < 32; kk++){
            float4 a0 = *(const float4*)(As + kk*AS_STRIDE + mg*4);
            float aa[4] = {a0.x, a0.y, a0.z, a0.w};
            unsigned long long aa2[4];
            #pragma unroll
            for (int i = 0; i < 4; i++) aa2[i] = packdup(aa[i]);
            const unsigned long long* bp =
                (const unsigned long long*)(Bs + kk*NC + ng*TN);
            unsigned long long bb2[TH];
            #pragma unroll
            for (int j = 0; j < TH; j++) bb2[j] = bp[j];
            #pragma unroll
            for (int i = 0; i < 4; i++)
                #pragma unroll
                for (int j = 0; j < TH; j++) fma2(acc2[i][j], aa2[i], bb2[j]);
        }
        __syncthreads();
    }
    #pragma unroll
    for (int i = 0; i < 4; i++){
        int row = m0 + mg*4 + i;
        if (row >= M) continue;
        #pragma unroll
        for (int j = 0; j < TH; j++){
            float vlo, vhi;
            unpack2(acc2[i][j], vlo, vhi);
            int col = ng*TN + 2*j;
            float val0 = vlo * alpha;
            float val1 = vhi * alpha;
            if (MODE == 2){
                val0 += D[row*96 + col];
                val1 += D[row*96 + col + 1];
                float sv0 = silu_f(val0);
                float sv1 = silu_f(val1);
                if (col < 64){
                    g_s[row*64 + col]   = sv0;
                    g_s[row*64 + col+1] = sv1;
                } else {
                    g_gate[row*32 + (col-64)]   = sv0;
                    g_gate[row*32 + (col-64)+1] = sv1;
                }
            } else {
                C[row*NC + col]   = val0;
                C[row*NC + col+1] = val1;
            }
        }
    }
}

#define A_SCS 0.0625f
#define A_S1  0.125f
#define A_V1  0.17677669529f
#define A_O   0.10206207262f

#define SM_FLOATS (32*AS_STRIDE + 32*96)

// phase A, layer 0: sc_s | l1_s
__global__ __launch_bounds__(256, 3)
void k_phA0(const float* __restrict__ nodes, const float* __restrict__ WscS,
            const float* __restrict__ Wl1s){
    __shared__ __align__(16) float sm[SM_FLOATS];
    int b = blockIdx.x;
    if (b < NB64s) gemm_body<256,96,1,256>(sm, g_s, WscS, nullptr, g_scs, nodes, Nn, A_SCS, b);
    else           gemm_body< 64,64,0, 64>(sm, g_s, Wl1s, nullptr, g_s1, nullptr, Nn, A_S1, b-NB64s);
}

// phase A, layer 1: sc_s | l1_s | gated l1_v
__global__ __launch_bounds__(256, 3)
void k_phA1(const float* __restrict__ nodes, const float* __restrict__ WscS,
            const float* __restrict__ Wl1s, const float* __restrict__ Wl1v){
    __shared__ __align__(16) float sm[SM_FLOATS];
    int b = blockIdx.x;
    if (b < NB64s)        gemm_body<256,96,1,256>(sm, g_s, WscS, nullptr, g_scs, nodes, Nn, A_SCS, b);
    else if (b < 2*NB64s) gemm_body< 64,64,0, 64>(sm, g_s, Wl1s, nullptr, g_s1, nullptr, Nn, A_S1, b-NB64s);
    else                  gemm_body< 32,32,5, 32>(sm, g_v, Wl1v, nullptr, g_v1, g_gate, 3*Nn, A_V1, b-2*NB64s);
}

// phase B, layer 0: l2_s (K=64 effective) | l2_v (K=64 effective)
__global__ __launch_bounds__(256, 3)
void k_phB0(const float* __restrict__ Wl2s, const float* __restrict__ Wl2v){
    __shared__ __align__(16) float sm[SM_FLOATS];
    int b = blockIdx.x;
    if (b < NB64s) gemm_body<64,96,2,96>(sm, g_as, Wl2s, g_scs, nullptr, nullptr, Nn, A_O, b);
    else           gemm_body<64,32,0,96>(sm, g_av, Wl2v, nullptr, g_v, nullptr, 3*Nn, A_O, b-NB64s);
}

// phase B, layer 1: l2_s only (full K=96)
__global__ __launch_bounds__(256, 3)
void k_phB1(const float* __restrict__ Wl2s){
    __shared__ __align__(16) float sm[SM_FLOATS];
    gemm_body<96,96,2,96>(sm, g_as, Wl2s, g_scs, nullptr, nullptr, Nn, A_O, blockIdx.x);
}

// ---------------- gather (lane l owns features 2l, 2l+1) ----------------
template<int LAYER>
__global__ void k_gather(){
    int n = blockIdx.x*8 + threadIdx.y;
    if (n >= Nn) return;
    int l = threadIdx.x;
    const __half2* tb_base = g_tabh + LAYER*(TAB*192);
    int beg = g_off[n], end = g_off[n+1];
    float as0 = 0.f, as1 = 0.f, as2 = 0.f;
    float av00=0,av01=0, av10=0,av11=0, av20=0,av21=0;
    #pragma unroll 4
    for (int p = beg; p < end; p++){
        float4 d = g_edir[p];
        int src = g_esrc[p];
        int gi = (int)d.x; gi = min(gi, TAB-1);
        float f = d.x - (float)gi;
        const __half2* t0 = tb_base + gi*192;
        H2x2 w1 = *reinterpret_cast<const H2x2*>(t0 + 2*l);
        float w1a = __low2float(w1.a) + f*__high2float(w1.a);
        float w1b = __low2float(w1.b) + f*__high2float(w1.b);
        float2 se = *reinterpret_cast<const float2*>(&g_s1[src*64 + 2*l]);
        as0 = fmaf(w1a, se.x, as0);
        as1 = fmaf(w1b, se.y, as1);
        if (LAYER == 0){
            H2x2 w2 = *reinterpret_cast<const H2x2*>(t0 + 64 + 2*l);
            float w2a = __low2float(w2.a) + f*__high2float(w2.a);
            float w2b = __low2float(w2.b) + f*__high2float(w2.b);
            float p2a = w2a*se.x, p2b = w2b*se.y;
            av00 = fmaf(p2a, d.y, av00); av10 = fmaf(p2a, d.z, av10); av20 = fmaf(p2a, d.w, av20);
            av01 = fmaf(p2b, d.y, av01); av11 = fmaf(p2b, d.z, av11); av21 = fmaf(p2b, d.w, av21);
        } else {
            __half2 h4 = t0[160 + l];
            float w4 = __low2float(h4) + f*__high2float(h4);
            float ve0 = g_v1[src*96 +      l];
            float ve1 = g_v1[src*96 + 32 + l];
            float ve2 = g_v1[src*96 + 64 + l];
            float dv = ve0*d.y + ve1*d.z + ve2*d.w;
            as2 = fmaf(w4*INV_SQRT3f, dv, as2);
        }
    }
    const float sc = 0.25f;
    *reinterpret_cast<float2*>(&g_as[n*96 + 2*l]) = make_float2(as0*sc, as1*sc);
    if (LAYER == 0){
        int b0 = n*288;
        *reinterpret_cast<float2*>(&g_av[b0 +       2*l]) = make_float2(av00*sc, av01*sc);
        *reinterpret_cast<float2*>(&g_av[b0 +  96 + 2*l]) = make_float2(av10*sc, av11*sc);
        *reinterpret_cast<float2*>(&g_av[b0 + 192 + 2*l]) = make_float2(av20*sc, av21*sc);
    } else {
        g_as[n*96 + 64 + l] = as2*sc;
    }
}

// ---------------- heads ----------------
__global__ void k_head(const float* __restrict__ nodes,
                       const float* __restrict__ Wen1, const float* __restrict__ Wen2,
                       const float* __restrict__ Wmag1, const float* __restrict__ Wmag2,
                       const float* __restrict__ sc_occ, const float* __restrict__ sh_occ,
                       const float* __restrict__ esc, const float* __restrict__ esh,
                       float* __restrict__ out){
    int n = blockIdx.x*8 + threadIdx.y;
    if (n >= Nn) return;
    int t = threadIdx.x;
    const float* s = g_s + n*64;
    float he = 0.f, hm = 0.f;
    #pragma unroll 8
    for (int i = 0; i < 64; i++){
        float si = s[i];
        he = fmaf(si, Wen1[i*32+t], he);
        hm = fmaf(si, Wmag1[i*32+t], hm);
    }
    he *= 0.125f; hm *= 0.125f;
    float pe  = he * Wen2[t];
    float pm0 = hm * Wmag2[t*2+0];
    float pm1 = hm * Wmag2[t*2+1];
    #pragma unroll
    for (int o = 16; o; o >>= 1){
        pe  += __shfl_down_sync(0xffffffffu, pe,  o);
        pm0 += __shfl_down_sync(0xffffffffu, pm0, o);
        pm1 += __shfl_down_sync(0xffffffffu, pm1, o);
    }
    if (t == 0){
        g_atomic[n] = esc[0] * (pe * 0.17677669529f) + esh[0];
        float a0 = nodes[n*4+0], a1 = nodes[n*4+1], a2 = nodes[n*4+2];
        float s0 = a0*sc_occ[0] + a1*sc_occ[2] + a2*sc_occ[4];
        float s1m= a0*sc_occ[1] + a1*sc_occ[3] + a2*sc_occ[5];
        float t0 = a0*sh_occ[0] + a1*sh_occ[2] + a2*sh_occ[4];
        float t1 = a0*sh_occ[1] + a1*sh_occ[3] + a2*sh_occ[5];
        out[Gg + n*2 + 0] = s0 *(pm0 * 0.17677669529f) + t0;
        out[Gg + n*2 + 1] = s1m*(pm1 * 0.17677669529f) + t1;
    }
}

__global__ void k_energy(const int* __restrict__ n_node, float* __restrict__ out){
    __shared__ float sm[256];
    int g = blockIdx.x, t = threadIdx.x;
    int start = 0;
    for (int q = 0; q < g; q++) start += n_node[q];
    int end = start + n_node[g];
    if (start > Nn) start = Nn;
    if (end > Nn) end = Nn;
    float acc = 0.f;
    for (int i = start + t; i < end; i += 256) acc += g_atomic[i];
    sm[t] = acc; __syncthreads();
    #pragma unroll
    for (int o = 128; o; o >>= 1){ if (t < o) sm[t] += sm[t+o]; __syncthreads(); }
    if (t == 0) out[g] = sm[0];
}

// ---------------- launch ----------------
extern "C" void kernel_launch(void* const* d_in, const int* in_sizes, int n_in,
                              void* d_out, int out_size){
    const float* nodes   = (const float*)d_in[0];
    const float* dR      = (const float*)d_in[1];
    const int*   senders = (const int*)  d_in[2];
    const int*   recv    = (const int*)  d_in[3];
    const int*   n_node  = (const int*)  d_in[4];
    const float* W_embed = (const float*)d_in[5];
    const float* W_sc_s  = (const float*)d_in[6];
    const float* W_l1_s  = (const float*)d_in[8];
    const float* W_l1_v  = (const float*)d_in[9];
    const float* Wr0     = (const float*)d_in[10];
    const float* Wr1     = (const float*)d_in[11];
    const float* Wr2     = (const float*)d_in[12];
    const float* W_l2_s  = (const float*)d_in[13];
    const float* W_l2_v  = (const float*)d_in[14];
    const float* W_en1   = (const float*)d_in[15];
    const float* W_en2   = (const float*)d_in[16];
    const float* W_mag1  = (const float*)d_in[17];
    const float* W_mag2  = (const float*)d_in[18];
    const float* sc_occ  = (const float*)d_in[19];
    const float* sh_occ  = (const float*)d_in[20];
    const float* esc     = (const float*)d_in[21];
    const float* esh     = (const float*)d_in[22];
    float* out = (float*)d_out;

    static cudaStream_t sA = nullptr, sB = nullptr;
    static cudaEvent_t evF = nullptr, evA = nullptr, evB = nullptr;
    if (sA == nullptr){
        cudaStreamCreateWithFlags(&sA, cudaStreamNonBlocking);
        cudaStreamCreateWithFlags(&sB, cudaStreamNonBlocking);
        cudaEventCreateWithFlags(&evF, cudaEventDisableTiming);
        cudaEventCreateWithFlags(&evA, cudaEventDisableTiming);
        cudaEventCreateWithFlags(&evB, cudaEventDisableTiming);
    }

    // fork
    cudaEventRecord(evF, 0);
    cudaStreamWaitEvent(sA, evF, 0);
    cudaStreamWaitEvent(sB, evF, 0);

    // stream 0: CSR chain + sort/records
    k_zero_init<<<(Nn + 255)/256, 256>>>();
    k_count<<<(Ee + 255)/256, 256>>>(recv);
    k_scan<<<1, 1024>>>();
    k_scatter<<<(Ee + 255)/256, 256>>>(recv);
    k_sortrec<<<SORT_NB, 256>>>(dR, senders);

    // stream A: embed -> phase A layer 0
    k_embed<<<(Nn*64 + 255)/256, 256, 0, sA>>>(nodes, W_embed);
    k_phA0<<<2*NB64s, 256, 0, sA>>>(nodes, W_sc_s, W_l1_s);

    // stream B: radial table -> half2 pack
    k_table<<<TAB_NB, 256, 0, sB>>>(Wr0, Wr1, Wr2);
    k_pack<<<(2*TAB*192 + 255)/256, 256, 0, sB>>>();

    // join
    cudaEventRecord(evA, sA);
    cudaEventRecord(evB, sB);
    cudaStreamWaitEvent(0, evA, 0);
    cudaStreamWaitEvent(0, evB, 0);

    // layer 0 tail
    k_gather<0><<<(Nn + 7)/8, dim3(32, 8)>>>();
    k_phB0<<<NB64s + NB64v, 256>>>(W_l2_s, W_l2_v);
    // layer 1
    k_phA1<<<2*NB64s + NB64v, 256>>>(nodes, W_sc_s + 24576, W_l1_s + 4096, W_l1_v + 1024);
    k_gather<1><<<(Nn + 7)/8, dim3(32, 8)>>>();
    k_phB1<<<NB64s, 256>>>(W_l2_s + 9216);

    k_head<<<(Nn + 7)/8, dim3(32, 8)>>>(nodes, W_en1, W_en2, W_mag1, W_mag2,
                                        sc_occ, sh_occ, esc, esh, out);
    k_energy<<<Gg, 256>>>(n_node, out);
}